// round 3
// baseline (speedup 1.0000x reference)
#include <cuda_runtime.h>
#include <math.h>

#define Bb 4
#define Ss 2048
#define Dd 1024
#define Hh 16
#define HDd 64
#define Uu 38
#define NR (Bb*Ss)
#define SCALE 0.125f

// ---------------- scratch (static device globals; no allocations) ----------------
__device__ float g_Q[Bb*Hh*Ss*HDd];
__device__ float g_K[Bb*Hh*Ss*HDd];
__device__ float g_V[Bb*Hh*Ss*HDd];
__device__ float g_Kmean[Bb*Hh*HDd];
__device__ float g_Vmean[Bb*Hh*HDd];
__device__ float g_imp[Bb*Hh*Ss];
__device__ int   g_selidx[Bb*Hh*Uu];
__device__ int   g_selu[Bb*Hh*Ss];
__device__ float g_outsel[Bb*Hh*Uu*HDd];
__device__ float g_base[Bb*Dd];

// ---------------- projection GEMM: C[n,j] = sum_k A[n,k]*W[j,k] + bias[j] ----------------
// Output stored head-major: C[b][h][s][hd], j = h*64+hd, n = b*2048+s.
__global__ __launch_bounds__(256) void proj_kernel(const float* __restrict__ A,
        const float* __restrict__ W, const float* __restrict__ bias, int which)
{
    float* C = (which==0) ? g_Q : (which==1) ? g_K : g_V;
    __shared__ float As[16][132];
    __shared__ float Ws[16][132];
    int n0 = blockIdx.x * 128;
    int j0 = blockIdx.y * 128;
    int tid = threadIdx.x;
    int tx = tid & 15, ty = tid >> 4;
    float acc[8][8];
    #pragma unroll
    for (int i=0;i<8;i++)
        #pragma unroll
        for (int j=0;j<8;j++) acc[i][j]=0.f;

    for (int k0=0;k0<Dd;k0+=16){
        #pragma unroll
        for (int i=0;i<2;i++){
            int g = tid*2+i;          // 0..511 float4 slots
            int row = g>>2, c4 = g&3;
            float4 v = *(const float4*)(A + (size_t)(n0+row)*Dd + k0 + c4*4);
            As[c4*4+0][row]=v.x; As[c4*4+1][row]=v.y; As[c4*4+2][row]=v.z; As[c4*4+3][row]=v.w;
            float4 w = *(const float4*)(W + (size_t)(j0+row)*Dd + k0 + c4*4);
            Ws[c4*4+0][row]=w.x; Ws[c4*4+1][row]=w.y; Ws[c4*4+2][row]=w.z; Ws[c4*4+3][row]=w.w;
        }
        __syncthreads();
        #pragma unroll
        for (int kk=0;kk<16;kk++){
            float a[8], b[8];
            *(float4*)&a[0] = *(float4*)&As[kk][ty*8];
            *(float4*)&a[4] = *(float4*)&As[kk][ty*8+4];
            *(float4*)&b[0] = *(float4*)&Ws[kk][tx*8];
            *(float4*)&b[4] = *(float4*)&Ws[kk][tx*8+4];
            #pragma unroll
            for (int i=0;i<8;i++)
                #pragma unroll
                for (int j=0;j<8;j++) acc[i][j] += a[i]*b[j];
        }
        __syncthreads();
    }
    #pragma unroll
    for (int i=0;i<8;i++){
        int n = n0 + ty*8 + i;
        int b = n >> 11, s = n & 2047;
        #pragma unroll
        for (int j=0;j<8;j++){
            int col = j0 + tx*8 + j;
            int h = col >> 6, hd = col & 63;
            C[((((size_t)b*Hh + h)*Ss + s)<<6) + hd] = acc[i][j] + __ldg(&bias[col]);
        }
    }
}

// ---------------- per-(b,h) means of K and V over sequence ----------------
__global__ void mean_kernel(){
    int bh = blockIdx.x;
    int tid = threadIdx.x;
    int hd = tid & 63, chunk = tid >> 6;
    const float* K = g_K + (size_t)bh*Ss*HDd;
    const float* V = g_V + (size_t)bh*Ss*HDd;
    float sk=0.f, sv=0.f;
    for (int s=chunk*512; s<chunk*512+512; s++){
        sk += K[(size_t)s*HDd+hd];
        sv += V[(size_t)s*HDd+hd];
    }
    __shared__ float rk[256], rv[256];
    rk[tid]=sk; rv[tid]=sv;
    __syncthreads();
    if (tid<64){
        float a = rk[tid]+rk[tid+64]+rk[tid+128]+rk[tid+192];
        float b = rv[tid]+rv[tid+64]+rv[tid+128]+rv[tid+192];
        g_Kmean[bh*64+tid] = a*(1.f/Ss);
        g_Vmean[bh*64+tid] = b*(1.f/Ss);
    }
}

// ---------------- importance scan: imp[q] = (max_k Q·K_k  -  Q·Kmean) * scale ----------------
__global__ __launch_bounds__(256) void scan_kernel(){
    int bh = blockIdx.y;
    int q0 = blockIdx.x * 128;
    const float* Q = g_Q + (size_t)bh*Ss*HDd;
    const float* K = g_K + (size_t)bh*Ss*HDd;
    __shared__ float Qs[64][132];   // [hd][q_local], Q tile persists across all k
    __shared__ float Ks[16][132];   // [hd_chunk][k_local]
    __shared__ float Km[64];
    __shared__ float qm[128];
    int tid = threadIdx.x;
    int tx = tid & 15, ty = tid >> 4;

    #pragma unroll
    for (int i=0;i<8;i++){
        int g = tid*8+i;            // 0..2047 float4 slots: 128 rows x 16 groups
        int row = g>>4, c4 = g&15;
        float4 v = *(const float4*)(Q + (size_t)(q0+row)*64 + c4*4);
        Qs[c4*4+0][row]=v.x; Qs[c4*4+1][row]=v.y; Qs[c4*4+2][row]=v.z; Qs[c4*4+3][row]=v.w;
    }
    if (tid<64) Km[tid] = g_Kmean[bh*64+tid];
    __syncthreads();

    float qmax[8];
    #pragma unroll
    for (int i=0;i<8;i++) qmax[i] = -INFINITY;

    for (int kt=0; kt<16; kt++){
        int k0 = kt*128;
        float acc[8][8];
        #pragma unroll
        for (int i=0;i<8;i++)
            #pragma unroll
            for (int j=0;j<8;j++) acc[i][j]=0.f;
        for (int hc=0; hc<4; hc++){
            #pragma unroll
            for (int i=0;i<2;i++){
                int g = tid*2+i; int row=g>>2, c4=g&3;
                float4 v = *(const float4*)(K + (size_t)(k0+row)*64 + hc*16 + c4*4);
                Ks[c4*4+0][row]=v.x; Ks[c4*4+1][row]=v.y; Ks[c4*4+2][row]=v.z; Ks[c4*4+3][row]=v.w;
            }
            __syncthreads();
            #pragma unroll
            for (int kk=0;kk<16;kk++){
                float a[8], b[8];
                *(float4*)&a[0] = *(float4*)&Qs[hc*16+kk][ty*8];
                *(float4*)&a[4] = *(float4*)&Qs[hc*16+kk][ty*8+4];
                *(float4*)&b[0] = *(float4*)&Ks[kk][tx*8];
                *(float4*)&b[4] = *(float4*)&Ks[kk][tx*8+4];
                #pragma unroll
                for (int i=0;i<8;i++)
                    #pragma unroll
                    for (int j=0;j<8;j++) acc[i][j] += a[i]*b[j];
            }
            __syncthreads();
        }
        #pragma unroll
        for (int i=0;i<8;i++)
            #pragma unroll
            for (int j=0;j<8;j++) qmax[i] = fmaxf(qmax[i], acc[i][j]);
    }
    // reduce across the 16 tx lanes (same ty stays inside half-warp for off<16)
    #pragma unroll
    for (int off=1; off<16; off<<=1){
        #pragma unroll
        for (int i=0;i<8;i++)
            qmax[i] = fmaxf(qmax[i], __shfl_xor_sync(0xffffffffu, qmax[i], off));
    }
    if (tx==0){
        #pragma unroll
        for (int i=0;i<8;i++) qm[ty*8+i] = qmax[i];
    }
    __syncthreads();
    if (tid < 128){
        int q = tid;
        float dot=0.f;
        #pragma unroll
        for (int hd=0; hd<64; hd++) dot += Qs[hd][q]*Km[hd];
        g_imp[(size_t)bh*Ss + q0 + q] = (qm[q] - dot)*SCALE;
    }
}

// ---------------- top-U selection per (b,h): iterative argmax, tie -> lower index ----------------
__global__ void topk_kernel(){
    int bh = blockIdx.x;
    int tid = threadIdx.x;
    __shared__ float vals[Ss];
    __shared__ float rv[256];
    __shared__ int   ri[256];
    for (int s=tid;s<Ss;s+=256){ vals[s]=g_imp[(size_t)bh*Ss+s]; g_selu[(size_t)bh*Ss+s]=-1; }
    __syncthreads();
    for (int it=0; it<Uu; it++){
        float bv=-INFINITY; int bi=Ss;
        for (int s=tid;s<Ss;s+=256){
            float v=vals[s];
            if (v>bv){ bv=v; bi=s; }
        }
        rv[tid]=bv; ri[tid]=bi;
        __syncthreads();
        for (int off=128; off>0; off>>=1){
            if (tid<off){
                float v2=rv[tid+off]; int i2=ri[tid+off];
                if (v2>rv[tid] || (v2==rv[tid] && i2<ri[tid])){ rv[tid]=v2; ri[tid]=i2; }
            }
            __syncthreads();
        }
        if (tid==0){
            int sel = ri[0];
            g_selidx[bh*Uu+it]=sel;
            g_selu[(size_t)bh*Ss+sel]=it;
            vals[sel]=-INFINITY;
        }
        __syncthreads();
    }
}

// ---------------- attention for selected queries: one block per (b,h,u) ----------------
__global__ __launch_bounds__(256) void attn_kernel(){
    int bh = blockIdx.x / Uu;
    int u  = blockIdx.x % Uu;
    int tid = threadIdx.x;
    __shared__ float sc[Ss];
    __shared__ float red[256];
    __shared__ float qv[64];
    int sq = g_selidx[bh*Uu+u];
    const float* Q = g_Q + ((size_t)bh*Ss + sq)*64;
    const float* K = g_K + (size_t)bh*Ss*64;
    const float* V = g_V + (size_t)bh*Ss*64;
    if (tid<64) qv[tid]=Q[tid];
    __syncthreads();
    float lm = -INFINITY;
    for (int k=tid;k<Ss;k+=256){
        const float4* kr = (const float4*)(K + (size_t)k*64);
        float d=0.f;
        #pragma unroll
        for (int c=0;c<16;c++){
            float4 kv = kr[c];
            float4 q4 = *(const float4*)&qv[c*4];
            d += kv.x*q4.x + kv.y*q4.y + kv.z*q4.z + kv.w*q4.w;
        }
        d *= SCALE;
        sc[k]=d;
        lm = fmaxf(lm,d);
    }
    red[tid]=lm; __syncthreads();
    for (int off=128;off>0;off>>=1){ if(tid<off) red[tid]=fmaxf(red[tid],red[tid+off]); __syncthreads(); }
    float mx = red[0];
    __syncthreads();
    float ls=0.f;
    for (int k=tid;k<Ss;k+=256){
        float e = expf(sc[k]-mx);
        sc[k]=e; ls+=e;
    }
    red[tid]=ls; __syncthreads();
    for (int off=128;off>0;off>>=1){ if(tid<off) red[tid]+=red[tid+off]; __syncthreads(); }
    float inv = 1.f/(red[0]+1e-8f);
    __syncthreads();
    int hd = tid & 63, chunk = tid >> 6;
    float acc=0.f;
    for (int k=chunk*512;k<chunk*512+512;k++)
        acc += sc[k]*V[(size_t)k*64+hd];
    red[tid]=acc; __syncthreads();
    if (tid<64){
        float o = (red[tid]+red[tid+64]+red[tid+128]+red[tid+192])*inv;
        g_outsel[(bh*Uu+u)*64+tid] = o;
    }
}

// ---------------- base[b][:] = meanVcat[b] @ Wo^T + bo ----------------
__global__ void base_kernel(const float* __restrict__ Wo, const float* __restrict__ bo){
    int b = blockIdx.y;
    int j = blockIdx.x*256 + threadIdx.x;
    __shared__ float mv[Dd];
    for (int d=threadIdx.x; d<Dd; d+=256) mv[d] = g_Vmean[b*Dd + d];
    __syncthreads();
    float acc = bo[j];
    const float* wr = Wo + (size_t)j*Dd;
    for (int d=0; d<Dd; d+=4){
        float4 w = *(const float4*)(wr+d);
        acc += w.x*mv[d] + w.y*mv[d+1] + w.z*mv[d+2] + w.w*mv[d+3];
    }
    g_base[b*Dd + j] = acc;
}

// ---------------- output assembly: base + sparse rank-64 corrections, one block per row ----------------
__global__ __launch_bounds__(256) void out_kernel(const float* __restrict__ Wo, float* __restrict__ out){
    int row = blockIdx.x;          // b*Ss + s
    int b = row >> 11, s = row & 2047;
    int tid = threadIdx.x;
    float acc[4];
    #pragma unroll
    for (int r=0;r<4;r++) acc[r] = g_base[b*Dd + tid + r*256];
    __shared__ float delta[64];
    for (int h=0;h<Hh;h++){
        int u = g_selu[((size_t)(b*Hh+h))*Ss + s];
        if (u>=0){   // uniform across block
            if (tid<64) delta[tid] = g_outsel[((b*Hh+h)*Uu+u)*64 + tid] - g_Vmean[(b*Hh+h)*64 + tid];
            __syncthreads();
            #pragma unroll
            for (int r=0;r<4;r++){
                int j = tid + r*256;
                const float* wr = Wo + (size_t)j*Dd + h*64;
                float a=0.f;
                #pragma unroll
                for (int k=0;k<64;k+=4){
                    float4 w=*(const float4*)(wr+k);
                    a += w.x*delta[k]+w.y*delta[k+1]+w.z*delta[k+2]+w.w*delta[k+3];
                }
                acc[r]+=a;
            }
            __syncthreads();
        }
    }
    #pragma unroll
    for (int r=0;r<4;r++) out[(size_t)row*Dd + tid + r*256] = acc[r];
}

// ---------------- launch ----------------
extern "C" void kernel_launch(void* const* d_in, const int* in_sizes, int n_in,
                              void* d_out, int out_size){
    const float* q  = (const float*)d_in[0];
    const float* k  = (const float*)d_in[1];
    const float* v  = (const float*)d_in[2];
    const float* Wq = (const float*)d_in[3];
    const float* bq = (const float*)d_in[4];
    const float* Wk = (const float*)d_in[5];
    const float* bk = (const float*)d_in[6];
    const float* Wv = (const float*)d_in[7];
    const float* bv = (const float*)d_in[8];
    const float* Wo = (const float*)d_in[9];
    const float* bo = (const float*)d_in[10];
    float* out = (float*)d_out;

    dim3 pg(NR/128, Dd/128);
    proj_kernel<<<pg,256>>>(q, Wq, bq, 0);
    proj_kernel<<<pg,256>>>(k, Wk, bk, 1);
    proj_kernel<<<pg,256>>>(v, Wv, bv, 2);
    mean_kernel<<<Bb*Hh,256>>>();
    scan_kernel<<<dim3(Ss/128, Bb*Hh),256>>>();
    topk_kernel<<<Bb*Hh,256>>>();
    attn_kernel<<<Bb*Hh*Uu,256>>>();
    base_kernel<<<dim3(Dd/256, Bb),256>>>(Wo, bo);
    out_kernel<<<NR,256>>>(Wo, out);
}

// round 4
// speedup vs baseline: 1.0640x; 1.0640x over previous
#include <cuda_runtime.h>
#include <math.h>

#define Bb 4
#define Ss 2048
#define Dd 1024
#define Hh 16
#define HDd 64
#define Uu 38
#define NR (Bb*Ss)
#define SCALE 0.125f

typedef unsigned long long ull;

// packed f32x2 helpers (FFMA2 — ptxas never emits this from C++; PTX only)
__device__ __forceinline__ void fma2(ull& d, ull a, ull b){
    asm("fma.rn.f32x2 %0, %1, %2, %3;" : "=l"(d) : "l"(a), "l"(b), "l"(d));
}
__device__ __forceinline__ ull pack2(float x, float y){
    ull r; asm("mov.b64 %0, {%1,%2};" : "=l"(r) : "f"(x), "f"(y)); return r;
}
__device__ __forceinline__ void unpack2(ull v, float& lo, float& hi){
    asm("mov.b64 {%0,%1}, %2;" : "=f"(lo), "=f"(hi) : "l"(v));
}

// ---------------- scratch (static device globals; no allocations) ----------------
__device__ float g_Q[Bb*Hh*Ss*HDd];
__device__ float g_K[Bb*Hh*Ss*HDd];
__device__ float g_V[Bb*Hh*Ss*HDd];
__device__ float g_Kmean[Bb*Hh*HDd];
__device__ float g_Vmean[Bb*Hh*HDd];
__device__ float g_imp[Bb*Hh*Ss];
__device__ int   g_selidx[Bb*Hh*Uu];
__device__ int   g_selu[Bb*Hh*Ss];
__device__ float g_outsel[Bb*Hh*Uu*HDd];
__device__ float g_base[Bb*Dd];

// ---------------- projection GEMM: C[n,j] = sum_k A[n,k]*W[j,k] + bias[j] ----------------
// Output stored head-major: C[b][h][s][hd], j = h*64+hd, n = b*2048+s.
__global__ __launch_bounds__(256) void proj_kernel(const float* __restrict__ A,
        const float* __restrict__ W, const float* __restrict__ bias, int which)
{
    float* C = (which==0) ? g_Q : (which==1) ? g_K : g_V;
    __shared__ float As[16][132];
    __shared__ float Ws[16][132];
    int n0 = blockIdx.x * 128;
    int j0 = blockIdx.y * 128;
    int tid = threadIdx.x;
    int tx = tid & 15, ty = tid >> 4;
    ull acc2[8][4];
    #pragma unroll
    for (int i=0;i<8;i++)
        #pragma unroll
        for (int j=0;j<4;j++) acc2[i][j]=0ull;   // (0.0f,0.0f)

    for (int k0=0;k0<Dd;k0+=16){
        #pragma unroll
        for (int i=0;i<2;i++){
            int g = tid*2+i;          // 0..511 float4 slots
            int row = g>>2, c4 = g&3;
            float4 v = *(const float4*)(A + (size_t)(n0+row)*Dd + k0 + c4*4);
            As[c4*4+0][row]=v.x; As[c4*4+1][row]=v.y; As[c4*4+2][row]=v.z; As[c4*4+3][row]=v.w;
            float4 w = *(const float4*)(W + (size_t)(j0+row)*Dd + k0 + c4*4);
            Ws[c4*4+0][row]=w.x; Ws[c4*4+1][row]=w.y; Ws[c4*4+2][row]=w.z; Ws[c4*4+3][row]=w.w;
        }
        __syncthreads();
        #pragma unroll
        for (int kk=0;kk<16;kk++){
            float a8[8];
            *(float4*)&a8[0] = *(float4*)&As[kk][ty*8];
            *(float4*)&a8[4] = *(float4*)&As[kk][ty*8+4];
            float4 bv0 = *(float4*)&Ws[kk][tx*8];
            float4 bv1 = *(float4*)&Ws[kk][tx*8+4];
            ull b2[4];
            b2[0]=pack2(bv0.x,bv0.y); b2[1]=pack2(bv0.z,bv0.w);
            b2[2]=pack2(bv1.x,bv1.y); b2[3]=pack2(bv1.z,bv1.w);
            #pragma unroll
            for (int i=0;i<8;i++){
                ull a2 = pack2(a8[i], a8[i]);
                #pragma unroll
                for (int j=0;j<4;j++) fma2(acc2[i][j], a2, b2[j]);
            }
        }
        __syncthreads();
    }
    #pragma unroll
    for (int i=0;i<8;i++){
        int n = n0 + ty*8 + i;
        int b = n >> 11, s = n & 2047;
        #pragma unroll
        for (int j=0;j<4;j++){
            float lo, hi;
            unpack2(acc2[i][j], lo, hi);
            int col = j0 + tx*8 + 2*j;
            int h0 = col >> 6, hd0 = col & 63;
            int h1 = (col+1) >> 6, hd1 = (col+1) & 63;
            C[((((size_t)b*Hh + h0)*Ss + s)<<6) + hd0] = lo + __ldg(&bias[col]);
            C[((((size_t)b*Hh + h1)*Ss + s)<<6) + hd1] = hi + __ldg(&bias[col+1]);
        }
    }
}

// ---------------- per-(b,h) means of K and V over sequence ----------------
__global__ void mean_kernel(){
    int bh = blockIdx.x;
    int tid = threadIdx.x;
    int hd = tid & 63, chunk = tid >> 6;
    const float* K = g_K + (size_t)bh*Ss*HDd;
    const float* V = g_V + (size_t)bh*Ss*HDd;
    float sk=0.f, sv=0.f;
    for (int s=chunk*512; s<chunk*512+512; s++){
        sk += K[(size_t)s*HDd+hd];
        sv += V[(size_t)s*HDd+hd];
    }
    __shared__ float rk[256], rv[256];
    rk[tid]=sk; rv[tid]=sv;
    __syncthreads();
    if (tid<64){
        float a = rk[tid]+rk[tid+64]+rk[tid+128]+rk[tid+192];
        float b = rv[tid]+rv[tid+64]+rv[tid+128]+rv[tid+192];
        g_Kmean[bh*64+tid] = a*(1.f/Ss);
        g_Vmean[bh*64+tid] = b*(1.f/Ss);
    }
}

// ---------------- importance scan: imp[q] = (max_k Q·K_k  -  Q·Kmean) * scale ----------------
__global__ __launch_bounds__(256) void scan_kernel(){
    int bh = blockIdx.y;
    int q0 = blockIdx.x * 128;
    const float* Q = g_Q + (size_t)bh*Ss*HDd;
    const float* K = g_K + (size_t)bh*Ss*HDd;
    __shared__ float Qs[64][132];   // [hd][q_local], Q tile persists across all k
    __shared__ float Ks[16][132];   // [hd_chunk][k_local]
    __shared__ float Km[64];
    __shared__ float qm[128];
    int tid = threadIdx.x;
    int tx = tid & 15, ty = tid >> 4;

    #pragma unroll
    for (int i=0;i<8;i++){
        int g = tid*8+i;            // 0..2047 float4 slots: 128 rows x 16 groups
        int row = g>>4, c4 = g&15;
        float4 v = *(const float4*)(Q + (size_t)(q0+row)*64 + c4*4);
        Qs[c4*4+0][row]=v.x; Qs[c4*4+1][row]=v.y; Qs[c4*4+2][row]=v.z; Qs[c4*4+3][row]=v.w;
    }
    if (tid<64) Km[tid] = g_Kmean[bh*64+tid];
    __syncthreads();

    float qmax[8];
    #pragma unroll
    for (int i=0;i<8;i++) qmax[i] = -INFINITY;

    for (int kt=0; kt<16; kt++){
        int k0 = kt*128;
        ull acc2[8][4];
        #pragma unroll
        for (int i=0;i<8;i++)
            #pragma unroll
            for (int j=0;j<4;j++) acc2[i][j]=0ull;
        for (int hc=0; hc<4; hc++){
            #pragma unroll
            for (int i=0;i<2;i++){
                int g = tid*2+i; int row=g>>2, c4=g&3;
                float4 v = *(const float4*)(K + (size_t)(k0+row)*64 + hc*16 + c4*4);
                Ks[c4*4+0][row]=v.x; Ks[c4*4+1][row]=v.y; Ks[c4*4+2][row]=v.z; Ks[c4*4+3][row]=v.w;
            }
            __syncthreads();
            #pragma unroll
            for (int kk=0;kk<16;kk++){
                float a8[8];
                *(float4*)&a8[0] = *(float4*)&Qs[hc*16+kk][ty*8];
                *(float4*)&a8[4] = *(float4*)&Qs[hc*16+kk][ty*8+4];
                float4 bv0 = *(float4*)&Ks[kk][tx*8];
                float4 bv1 = *(float4*)&Ks[kk][tx*8+4];
                ull b2[4];
                b2[0]=pack2(bv0.x,bv0.y); b2[1]=pack2(bv0.z,bv0.w);
                b2[2]=pack2(bv1.x,bv1.y); b2[3]=pack2(bv1.z,bv1.w);
                #pragma unroll
                for (int i=0;i<8;i++){
                    ull a2 = pack2(a8[i], a8[i]);
                    #pragma unroll
                    for (int j=0;j<4;j++) fma2(acc2[i][j], a2, b2[j]);
                }
            }
            __syncthreads();
        }
        #pragma unroll
        for (int i=0;i<8;i++)
            #pragma unroll
            for (int j=0;j<4;j++){
                float lo, hi;
                unpack2(acc2[i][j], lo, hi);
                qmax[i] = fmaxf(qmax[i], fmaxf(lo, hi));
            }
    }
    // reduce across the 16 tx lanes (same ty stays inside half-warp for off<16)
    #pragma unroll
    for (int off=1; off<16; off<<=1){
        #pragma unroll
        for (int i=0;i<8;i++)
            qmax[i] = fmaxf(qmax[i], __shfl_xor_sync(0xffffffffu, qmax[i], off));
    }
    if (tx==0){
        #pragma unroll
        for (int i=0;i<8;i++) qm[ty*8+i] = qmax[i];
    }
    __syncthreads();
    if (tid < 128){
        int q = tid;
        float dot=0.f;
        #pragma unroll
        for (int hd=0; hd<64; hd++) dot += Qs[hd][q]*Km[hd];
        g_imp[(size_t)bh*Ss + q0 + q] = (qm[q] - dot)*SCALE;
    }
}

// ---------------- top-U selection per (b,h): iterative argmax, tie -> lower index ----------------
__global__ void topk_kernel(){
    int bh = blockIdx.x;
    int tid = threadIdx.x;
    __shared__ float vals[Ss];
    __shared__ float rv[256];
    __shared__ int   ri[256];
    for (int s=tid;s<Ss;s+=256){ vals[s]=g_imp[(size_t)bh*Ss+s]; g_selu[(size_t)bh*Ss+s]=-1; }
    __syncthreads();
    for (int it=0; it<Uu; it++){
        float bv=-INFINITY; int bi=Ss;
        for (int s=tid;s<Ss;s+=256){
            float v=vals[s];
            if (v>bv){ bv=v; bi=s; }
        }
        rv[tid]=bv; ri[tid]=bi;
        __syncthreads();
        for (int off=128; off>0; off>>=1){
            if (tid<off){
                float v2=rv[tid+off]; int i2=ri[tid+off];
                if (v2>rv[tid] || (v2==rv[tid] && i2<ri[tid])){ rv[tid]=v2; ri[tid]=i2; }
            }
            __syncthreads();
        }
        if (tid==0){
            int sel = ri[0];
            g_selidx[bh*Uu+it]=sel;
            g_selu[(size_t)bh*Ss+sel]=it;
            vals[sel]=-INFINITY;
        }
        __syncthreads();
    }
}

// ---------------- attention for selected queries: one block per (b,h,u) ----------------
__global__ __launch_bounds__(256) void attn_kernel(){
    int bh = blockIdx.x / Uu;
    int u  = blockIdx.x % Uu;
    int tid = threadIdx.x;
    __shared__ float sc[Ss];
    __shared__ float red[256];
    __shared__ float qv[64];
    int sq = g_selidx[bh*Uu+u];
    const float* Q = g_Q + ((size_t)bh*Ss + sq)*64;
    const float* K = g_K + (size_t)bh*Ss*64;
    const float* V = g_V + (size_t)bh*Ss*64;
    if (tid<64) qv[tid]=Q[tid];
    __syncthreads();
    float lm = -INFINITY;
    for (int k=tid;k<Ss;k+=256){
        const float4* kr = (const float4*)(K + (size_t)k*64);
        float d=0.f;
        #pragma unroll
        for (int c=0;c<16;c++){
            float4 kv = kr[c];
            float4 q4 = *(const float4*)&qv[c*4];
            d += kv.x*q4.x + kv.y*q4.y + kv.z*q4.z + kv.w*q4.w;
        }
        d *= SCALE;
        sc[k]=d;
        lm = fmaxf(lm,d);
    }
    red[tid]=lm; __syncthreads();
    for (int off=128;off>0;off>>=1){ if(tid<off) red[tid]=fmaxf(red[tid],red[tid+off]); __syncthreads(); }
    float mx = red[0];
    __syncthreads();
    float ls=0.f;
    for (int k=tid;k<Ss;k+=256){
        float e = expf(sc[k]-mx);
        sc[k]=e; ls+=e;
    }
    red[tid]=ls; __syncthreads();
    for (int off=128;off>0;off>>=1){ if(tid<off) red[tid]+=red[tid+off]; __syncthreads(); }
    float inv = 1.f/(red[0]+1e-8f);
    __syncthreads();
    int hd = tid & 63, chunk = tid >> 6;
    float acc=0.f;
    for (int k=chunk*512;k<chunk*512+512;k++)
        acc += sc[k]*V[(size_t)k*64+hd];
    red[tid]=acc; __syncthreads();
    if (tid<64){
        float o = (red[tid]+red[tid+64]+red[tid+128]+red[tid+192])*inv;
        g_outsel[(bh*Uu+u)*64+tid] = o;
    }
}

// ---------------- base[b][:] = meanVcat[b] @ Wo^T + bo ----------------
__global__ void base_kernel(const float* __restrict__ Wo, const float* __restrict__ bo){
    int b = blockIdx.y;
    int j = blockIdx.x*256 + threadIdx.x;
    __shared__ float mv[Dd];
    for (int d=threadIdx.x; d<Dd; d+=256) mv[d] = g_Vmean[b*Dd + d];
    __syncthreads();
    float acc = bo[j];
    const float* wr = Wo + (size_t)j*Dd;
    for (int d=0; d<Dd; d+=4){
        float4 w = *(const float4*)(wr+d);
        acc += w.x*mv[d] + w.y*mv[d+1] + w.z*mv[d+2] + w.w*mv[d+3];
    }
    g_base[b*Dd + j] = acc;
}

// ---------------- output assembly: base + sparse rank-64 corrections, one block per row ----------------
__global__ __launch_bounds__(256) void out_kernel(const float* __restrict__ Wo, float* __restrict__ out){
    int row = blockIdx.x;          // b*Ss + s
    int b = row >> 11, s = row & 2047;
    int tid = threadIdx.x;
    float acc[4];
    #pragma unroll
    for (int r=0;r<4;r++) acc[r] = g_base[b*Dd + tid + r*256];
    __shared__ float delta[64];
    for (int h=0;h<Hh;h++){
        int u = g_selu[((size_t)(b*Hh+h))*Ss + s];
        if (u>=0){   // uniform across block
            if (tid<64) delta[tid] = g_outsel[((b*Hh+h)*Uu+u)*64 + tid] - g_Vmean[(b*Hh+h)*64 + tid];
            __syncthreads();
            #pragma unroll
            for (int r=0;r<4;r++){
                int j = tid + r*256;
                const float* wr = Wo + (size_t)j*Dd + h*64;
                float a=0.f;
                #pragma unroll
                for (int k=0;k<64;k+=4){
                    float4 w=*(const float4*)(wr+k);
                    a += w.x*delta[k]+w.y*delta[k+1]+w.z*delta[k+2]+w.w*delta[k+3];
                }
                acc[r]+=a;
            }
            __syncthreads();
        }
    }
    #pragma unroll
    for (int r=0;r<4;r++) out[(size_t)row*Dd + tid + r*256] = acc[r];
}

// ---------------- launch ----------------
extern "C" void kernel_launch(void* const* d_in, const int* in_sizes, int n_in,
                              void* d_out, int out_size){
    const float* q  = (const float*)d_in[0];
    const float* k  = (const float*)d_in[1];
    const float* v  = (const float*)d_in[2];
    const float* Wq = (const float*)d_in[3];
    const float* bq = (const float*)d_in[4];
    const float* Wk = (const float*)d_in[5];
    const float* bk = (const float*)d_in[6];
    const float* Wv = (const float*)d_in[7];
    const float* bv = (const float*)d_in[8];
    const float* Wo = (const float*)d_in[9];
    const float* bo = (const float*)d_in[10];
    float* out = (float*)d_out;

    dim3 pg(NR/128, Dd/128);
    proj_kernel<<<pg,256>>>(q, Wq, bq, 0);
    proj_kernel<<<pg,256>>>(k, Wk, bk, 1);
    proj_kernel<<<pg,256>>>(v, Wv, bv, 2);
    mean_kernel<<<Bb*Hh,256>>>();
    scan_kernel<<<dim3(Ss/128, Bb*Hh),256>>>();
    topk_kernel<<<Bb*Hh,256>>>();
    attn_kernel<<<Bb*Hh*Uu,256>>>();
    base_kernel<<<dim3(Dd/256, Bb),256>>>(Wo, bo);
    out_kernel<<<NR,256>>>(Wo, out);
}

// round 7
// speedup vs baseline: 1.5736x; 1.4789x over previous
#include <cuda_runtime.h>
#include <cuda_bf16.h>
#include <math.h>

#define Bb 4
#define Ss 2048
#define Dd 1024
#define Hh 16
#define HDd 64
#define Uu 38
#define NR (Bb*Ss)
#define SCALE 0.125f
#define NIN (NR*Dd)       // 8388608
#define NW  (Dd*Dd)       // 1048576

// ---------------- scratch (static device globals; no allocations) ----------------
__device__ float g_Q[Bb*Hh*Ss*HDd];
__device__ float g_K[Bb*Hh*Ss*HDd];
__device__ float g_V[Bb*Hh*Ss*HDd];
__device__ float g_Kmean[Bb*Hh*HDd];
__device__ float g_Vmean[Bb*Hh*HDd];
__device__ float g_imp[Bb*Hh*Ss];
__device__ int   g_selidx[Bb*Hh*Uu];
__device__ int   g_selu[Bb*Hh*Ss];
__device__ float g_outsel[Bb*Hh*Uu*HDd];
__device__ float g_base[Bb*Dd];

// bf16 split copies of inputs / weights (row-major, same layout as source)
__device__ __nv_bfloat16 s_qh[NIN], s_ql[NIN];
__device__ __nv_bfloat16 s_kh[NIN], s_kl[NIN];
__device__ __nv_bfloat16 s_vh[NIN], s_vl[NIN];
__device__ __nv_bfloat16 w_qh[NW],  w_ql[NW];
__device__ __nv_bfloat16 w_kh[NW],  w_kl[NW];
__device__ __nv_bfloat16 w_vh[NW],  w_vl[NW];
// bf16 split copies of projected Q,K (head-major: [bh][s][hd])
__device__ __nv_bfloat16 g_Qh[NIN], g_Ql[NIN];
__device__ __nv_bfloat16 g_Kh[NIN], g_Kl[NIN];

// ---------------- helpers ----------------
__device__ __forceinline__ void splitf(float x, __nv_bfloat16& h, __nv_bfloat16& l){
    h = __float2bfloat16(x);
    l = __float2bfloat16(x - __bfloat162float(h));
}

__device__ __forceinline__ void mma16816(float* d, const unsigned* a, const unsigned* b){
    asm volatile("mma.sync.aligned.m16n8k16.row.col.f32.bf16.bf16.f32 "
        "{%0,%1,%2,%3}, {%4,%5,%6,%7}, {%8,%9}, {%0,%1,%2,%3};"
        : "+f"(d[0]), "+f"(d[1]), "+f"(d[2]), "+f"(d[3])
        : "r"(a[0]), "r"(a[1]), "r"(a[2]), "r"(a[3]), "r"(b[0]), "r"(b[1]));
}

// ---------------- split fp32 -> bf16 hi/lo ----------------
__global__ void split_kernel(const float* __restrict__ in, int which, int n4){
    __nv_bfloat16 *hi, *lo;
    switch(which){
        case 0: hi=s_qh; lo=s_ql; break;
        case 1: hi=s_kh; lo=s_kl; break;
        case 2: hi=s_vh; lo=s_vl; break;
        case 3: hi=w_qh; lo=w_ql; break;
        case 4: hi=w_kh; lo=w_kl; break;
        default:hi=w_vh; lo=w_vl; break;
    }
    int i = blockIdx.x*256 + threadIdx.x;
    if (i >= n4) return;
    float4 v = ((const float4*)in)[i];
    __nv_bfloat16 h0,h1,h2,h3,l0,l1,l2,l3;
    splitf(v.x,h0,l0); splitf(v.y,h1,l1); splitf(v.z,h2,l2); splitf(v.w,h3,l3);
    __nv_bfloat162 p;
    p.x=h0; p.y=h1; ((__nv_bfloat162*)hi)[2*i]   = p;
    p.x=h2; p.y=h3; ((__nv_bfloat162*)hi)[2*i+1] = p;
    p.x=l0; p.y=l1; ((__nv_bfloat162*)lo)[2*i]   = p;
    p.x=l2; p.y=l3; ((__nv_bfloat162*)lo)[2*i+1] = p;
}

// ---------------- projection GEMM via tensor cores (3xBF16 split) ----------------
// C[n,j] = sum_k A[n,k]*W[j,k] + bias[j]; output head-major fp32 (+bf16 hi/lo for Q,K)
__global__ __launch_bounds__(256) void proj_mma(const float* __restrict__ bias, int which){
    const __nv_bfloat16 *Ah_g, *Al_g, *Wh_g, *Wl_g;
    float* C;
    __nv_bfloat16 *Ch_g=nullptr, *Cl_g=nullptr;
    if (which==0){ Ah_g=s_qh; Al_g=s_ql; Wh_g=w_qh; Wl_g=w_ql; C=g_Q; Ch_g=g_Qh; Cl_g=g_Ql; }
    else if (which==1){ Ah_g=s_kh; Al_g=s_kl; Wh_g=w_kh; Wl_g=w_kl; C=g_K; Ch_g=g_Kh; Cl_g=g_Kl; }
    else { Ah_g=s_vh; Al_g=s_vl; Wh_g=w_vh; Wl_g=w_vl; C=g_V; }

    __shared__ __nv_bfloat16 Ah[128][40], Al[128][40], Bh[128][40], Bl[128][40];
    int n0 = blockIdx.x*128, j0 = blockIdx.y*128;
    int tid = threadIdx.x, lid = tid&31, wid = tid>>5;
    int wm = wid&1, wn = wid>>1;    // warp grid 2(m) x 4(n): 64 rows x 32 cols per warp
    float D[4][4][4];
    #pragma unroll
    for (int a=0;a<4;a++)
        #pragma unroll
        for (int b=0;b<4;b++)
            #pragma unroll
            for (int c=0;c<4;c++) D[a][b][c]=0.f;

    for (int kc=0; kc<Dd; kc+=32){
        // full tile fill: 128 rows x 4 uint4-slots = 512 slots, 2 per thread
        #pragma unroll
        for (int i=0;i<2;i++){
            int idx = tid*2+i;
            int row = idx>>2, slot = idx&3;
            *(uint4*)&Ah[row][slot*8] = *(const uint4*)(Ah_g + (size_t)(n0+row)*Dd + kc + slot*8);
            *(uint4*)&Al[row][slot*8] = *(const uint4*)(Al_g + (size_t)(n0+row)*Dd + kc + slot*8);
            *(uint4*)&Bh[row][slot*8] = *(const uint4*)(Wh_g + (size_t)(j0+row)*Dd + kc + slot*8);
            *(uint4*)&Bl[row][slot*8] = *(const uint4*)(Wl_g + (size_t)(j0+row)*Dd + kc + slot*8);
        }
        __syncthreads();
        #pragma unroll
        for (int ks=0; ks<2; ks++){
            int kof = ks*16 + (lid&3)*2;
            unsigned bh_[4][2], bl_[4][2];
            #pragma unroll
            for (int nt=0;nt<4;nt++){
                int cb = wn*32 + nt*8 + (lid>>2);
                bh_[nt][0] = *(const unsigned*)&Bh[cb][kof];
                bh_[nt][1] = *(const unsigned*)&Bh[cb][kof+8];
                bl_[nt][0] = *(const unsigned*)&Bl[cb][kof];
                bl_[nt][1] = *(const unsigned*)&Bl[cb][kof+8];
            }
            #pragma unroll
            for (int mt=0;mt<4;mt++){
                int rb = wm*64 + mt*16 + (lid>>2);
                unsigned ah_[4], al_[4];
                ah_[0]=*(const unsigned*)&Ah[rb][kof];
                ah_[1]=*(const unsigned*)&Ah[rb+8][kof];
                ah_[2]=*(const unsigned*)&Ah[rb][kof+8];
                ah_[3]=*(const unsigned*)&Ah[rb+8][kof+8];
                al_[0]=*(const unsigned*)&Al[rb][kof];
                al_[1]=*(const unsigned*)&Al[rb+8][kof];
                al_[2]=*(const unsigned*)&Al[rb][kof+8];
                al_[3]=*(const unsigned*)&Al[rb+8][kof+8];
                #pragma unroll
                for (int nt=0;nt<4;nt++){
                    mma16816(D[mt][nt], ah_, bh_[nt]);
                    mma16816(D[mt][nt], ah_, bl_[nt]);
                    mma16816(D[mt][nt], al_, bh_[nt]);
                }
            }
        }
        __syncthreads();
    }
    // epilogue
    #pragma unroll
    for (int mt=0;mt<4;mt++){
        int r0 = n0 + wm*64 + mt*16 + (lid>>2);
        #pragma unroll
        for (int nt=0;nt<4;nt++){
            int c0 = j0 + wn*32 + nt*8 + (lid&3)*2;
            float b0 = __ldg(&bias[c0]), b1 = __ldg(&bias[c0+1]);
            float v00 = D[mt][nt][0] + b0, v01 = D[mt][nt][1] + b1;
            float v10 = D[mt][nt][2] + b0, v11 = D[mt][nt][3] + b1;
            int h = c0 >> 6, hd = c0 & 63;
            #pragma unroll
            for (int rr=0;rr<2;rr++){
                int n = r0 + rr*8;
                int bb = n >> 11, s = n & 2047;
                size_t idx = (((size_t)(bb*Hh + h)*Ss + s)<<6) + hd;
                float lo = rr ? v10 : v00;
                float hi = rr ? v11 : v01;
                float2 fv; fv.x=lo; fv.y=hi;
                *(float2*)&C[idx] = fv;
                if (Ch_g){
                    __nv_bfloat16 h0,h1,l0,l1;
                    splitf(lo,h0,l0); splitf(hi,h1,l1);
                    __nv_bfloat162 p;
                    p.x=h0; p.y=h1; *(__nv_bfloat162*)&Ch_g[idx]=p;
                    p.x=l0; p.y=l1; *(__nv_bfloat162*)&Cl_g[idx]=p;
                }
            }
        }
    }
}

// ---------------- per-(b,h) means of K and V over sequence ----------------
__global__ void mean_kernel(){
    int bh = blockIdx.x;
    int tid = threadIdx.x;
    int hd = tid & 63, chunk = tid >> 6;
    const float* K = g_K + (size_t)bh*Ss*HDd;
    const float* V = g_V + (size_t)bh*Ss*HDd;
    float sk=0.f, sv=0.f;
    for (int s=chunk*512; s<chunk*512+512; s++){
        sk += K[(size_t)s*HDd+hd];
        sv += V[(size_t)s*HDd+hd];
    }
    __shared__ float rk[256], rv[256];
    rk[tid]=sk; rv[tid]=sv;
    __syncthreads();
    if (tid<64){
        float a = rk[tid]+rk[tid+64]+rk[tid+128]+rk[tid+192];
        float b = rv[tid]+rv[tid+64]+rv[tid+128]+rv[tid+192];
        g_Kmean[bh*64+tid] = a*(1.f/Ss);
        g_Vmean[bh*64+tid] = b*(1.f/Ss);
    }
}

// ---------------- importance scan via tensor cores ----------------
// imp[q] = (max_k Q.K_k - Q.Kmean) * scale
__global__ __launch_bounds__(256) void scan_mma(){
    extern __shared__ __nv_bfloat16 sm[];
    __nv_bfloat16* Qh = sm;                 // [128][72]
    __nv_bfloat16* Ql = sm + 128*72;
    __nv_bfloat16* Kh = sm + 2*128*72;
    __nv_bfloat16* Kl = sm + 3*128*72;
    __shared__ float Km[64];
    __shared__ float qmw[2][128];
    int bh = blockIdx.y, q0 = blockIdx.x*128;
    int tid = threadIdx.x, lid = tid&31, wid = tid>>5;
    int wm = wid&3, wn = wid>>2;  // warp grid 4(m) x 2(n): 32 q-rows x 64 keys per warp

    const __nv_bfloat16* Qh_g = g_Qh + ((size_t)bh*Ss + q0)*64;
    const __nv_bfloat16* Ql_g = g_Ql + ((size_t)bh*Ss + q0)*64;
    // full tile fill: 128 rows x 8 uint4-slots = 1024 slots, 4 per thread
    #pragma unroll
    for (int i=0;i<4;i++){
        int idx = tid*4+i;
        int row = idx>>3, slot = idx&7;
        *(uint4*)&Qh[row*72 + slot*8] = *(const uint4*)(Qh_g + (size_t)row*64 + slot*8);
        *(uint4*)&Ql[row*72 + slot*8] = *(const uint4*)(Ql_g + (size_t)row*64 + slot*8);
    }
    if (tid<64) Km[tid] = g_Kmean[bh*64+tid];
    ((float*)qmw)[tid] = -INFINITY;
    __syncthreads();

    // hoist Q fragments (reused across all 16 key chunks)
    unsigned qh_f[2][4][4], ql_f[2][4][4];
    #pragma unroll
    for (int mt=0;mt<2;mt++){
        int rb = wm*32 + mt*16 + (lid>>2);
        #pragma unroll
        for (int ks=0;ks<4;ks++){
            int kof = ks*16 + (lid&3)*2;
            qh_f[mt][ks][0]=*(const unsigned*)&Qh[rb*72+kof];
            qh_f[mt][ks][1]=*(const unsigned*)&Qh[(rb+8)*72+kof];
            qh_f[mt][ks][2]=*(const unsigned*)&Qh[rb*72+kof+8];
            qh_f[mt][ks][3]=*(const unsigned*)&Qh[(rb+8)*72+kof+8];
            ql_f[mt][ks][0]=*(const unsigned*)&Ql[rb*72+kof];
            ql_f[mt][ks][1]=*(const unsigned*)&Ql[(rb+8)*72+kof];
            ql_f[mt][ks][2]=*(const unsigned*)&Ql[rb*72+kof+8];
            ql_f[mt][ks][3]=*(const unsigned*)&Ql[(rb+8)*72+kof+8];
        }
    }

    float rmax[2][2];
    rmax[0][0]=rmax[0][1]=rmax[1][0]=rmax[1][1]=-INFINITY;

    const __nv_bfloat16* Kh_g = g_Kh + (size_t)bh*Ss*64;
    const __nv_bfloat16* Kl_g = g_Kl + (size_t)bh*Ss*64;
    for (int kt=0; kt<16; kt++){
        #pragma unroll
        for (int i=0;i<4;i++){
            int idx = tid*4+i;
            int row = idx>>3, slot = idx&7;
            *(uint4*)&Kh[row*72 + slot*8] = *(const uint4*)(Kh_g + (size_t)(kt*128+row)*64 + slot*8);
            *(uint4*)&Kl[row*72 + slot*8] = *(const uint4*)(Kl_g + (size_t)(kt*128+row)*64 + slot*8);
        }
        __syncthreads();
        #pragma unroll
        for (int nt=0;nt<8;nt++){
            int cb = wn*64 + nt*8 + (lid>>2);
            unsigned bhf[4][2], blf[4][2];
            #pragma unroll
            for (int ks=0;ks<4;ks++){
                int kof = ks*16 + (lid&3)*2;
                bhf[ks][0]=*(const unsigned*)&Kh[cb*72+kof];
                bhf[ks][1]=*(const unsigned*)&Kh[cb*72+kof+8];
                blf[ks][0]=*(const unsigned*)&Kl[cb*72+kof];
                blf[ks][1]=*(const unsigned*)&Kl[cb*72+kof+8];
            }
            #pragma unroll
            for (int mt=0;mt<2;mt++){
                float Dr[4] = {0.f,0.f,0.f,0.f};
                #pragma unroll
                for (int ks=0;ks<4;ks++){
                    mma16816(Dr, qh_f[mt][ks], bhf[ks]);
                    mma16816(Dr, qh_f[mt][ks], blf[ks]);
                    mma16816(Dr, ql_f[mt][ks], bhf[ks]);
                }
                rmax[mt][0] = fmaxf(rmax[mt][0], fmaxf(Dr[0], Dr[1]));
                rmax[mt][1] = fmaxf(rmax[mt][1], fmaxf(Dr[2], Dr[3]));
            }
        }
        __syncthreads();
    }
    // reduce over the 4 lanes sharing a row (lid&3)
    #pragma unroll
    for (int off=1; off<4; off<<=1){
        #pragma unroll
        for (int mt=0;mt<2;mt++){
            rmax[mt][0] = fmaxf(rmax[mt][0], __shfl_xor_sync(0xffffffffu, rmax[mt][0], off));
            rmax[mt][1] = fmaxf(rmax[mt][1], __shfl_xor_sync(0xffffffffu, rmax[mt][1], off));
        }
    }
    if ((lid&3)==0){
        #pragma unroll
        for (int mt=0;mt<2;mt++){
            int ql = wm*32 + mt*16 + (lid>>2);
            qmw[wn][ql]   = rmax[mt][0];
            qmw[wn][ql+8] = rmax[mt][1];
        }
    }
    __syncthreads();
    if (tid < 128){
        float mx = fmaxf(qmw[0][tid], qmw[1][tid]);
        const float* qrow = g_Q + ((size_t)bh*Ss + q0 + tid)*64;
        float dot = 0.f;
        #pragma unroll
        for (int c=0;c<16;c++){
            float4 qv = *(const float4*)(qrow + c*4);
            dot += qv.x*Km[c*4] + qv.y*Km[c*4+1] + qv.z*Km[c*4+2] + qv.w*Km[c*4+3];
        }
        g_imp[(size_t)bh*Ss + q0 + tid] = (mx - dot)*SCALE;
    }
}

// ---------------- top-U selection per (b,h): iterative argmax, tie -> lower index ----------------
__global__ void topk_kernel(){
    int bh = blockIdx.x;
    int tid = threadIdx.x;
    __shared__ float vals[Ss];
    __shared__ float rv[256];
    __shared__ int   ri[256];
    for (int s=tid;s<Ss;s+=256){ vals[s]=g_imp[(size_t)bh*Ss+s]; g_selu[(size_t)bh*Ss+s]=-1; }
    __syncthreads();
    for (int it=0; it<Uu; it++){
        float bv=-INFINITY; int bi=Ss;
        for (int s=tid;s<Ss;s+=256){
            float v=vals[s];
            if (v>bv){ bv=v; bi=s; }
        }
        rv[tid]=bv; ri[tid]=bi;
        __syncthreads();
        for (int off=128; off>0; off>>=1){
            if (tid<off){
                float v2=rv[tid+off]; int i2=ri[tid+off];
                if (v2>rv[tid] || (v2==rv[tid] && i2<ri[tid])){ rv[tid]=v2; ri[tid]=i2; }
            }
            __syncthreads();
        }
        if (tid==0){
            int sel = ri[0];
            g_selidx[bh*Uu+it]=sel;
            g_selu[(size_t)bh*Ss+sel]=it;
            vals[sel]=-INFINITY;
        }
        __syncthreads();
    }
}

// ---------------- attention for selected queries: one block per (b,h,u) ----------------
__global__ __launch_bounds__(256) void attn_kernel(){
    int bh = blockIdx.x / Uu;
    int u  = blockIdx.x % Uu;
    int tid = threadIdx.x;
    __shared__ float sc[Ss];
    __shared__ float red[256];
    __shared__ float qv[64];
    int sq = g_selidx[bh*Uu+u];
    const float* Q = g_Q + ((size_t)bh*Ss + sq)*64;
    const float* K = g_K + (size_t)bh*Ss*64;
    const float* V = g_V + (size_t)bh*Ss*64;
    if (tid<64) qv[tid]=Q[tid];
    __syncthreads();
    float lm = -INFINITY;
    for (int k=tid;k<Ss;k+=256){
        const float4* kr = (const float4*)(K + (size_t)k*64);
        float d=0.f;
        #pragma unroll
        for (int c=0;c<16;c++){
            float4 kv = kr[c];
            float4 q4 = *(const float4*)&qv[c*4];
            d += kv.x*q4.x + kv.y*q4.y + kv.z*q4.z + kv.w*q4.w;
        }
        d *= SCALE;
        sc[k]=d;
        lm = fmaxf(lm,d);
    }
    red[tid]=lm; __syncthreads();
    for (int off=128;off>0;off>>=1){ if(tid<off) red[tid]=fmaxf(red[tid],red[tid+off]); __syncthreads(); }
    float mx = red[0];
    __syncthreads();
    float ls=0.f;
    for (int k=tid;k<Ss;k+=256){
        float e = expf(sc[k]-mx);
        sc[k]=e; ls+=e;
    }
    red[tid]=ls; __syncthreads();
    for (int off=128;off>0;off>>=1){ if(tid<off) red[tid]+=red[tid+off]; __syncthreads(); }
    float inv = 1.f/(red[0]+1e-8f);
    __syncthreads();
    int hd = tid & 63, chunk = tid >> 6;
    float acc=0.f;
    for (int k=chunk*512;k<chunk*512+512;k++)
        acc += sc[k]*V[(size_t)k*64+hd];
    red[tid]=acc; __syncthreads();
    if (tid<64){
        float o = (red[tid]+red[tid+64]+red[tid+128]+red[tid+192])*inv;
        g_outsel[(bh*Uu+u)*64+tid] = o;
    }
}

// ---------------- base[b][:] = meanVcat[b] @ Wo^T + bo ----------------
__global__ void base_kernel(const float* __restrict__ Wo, const float* __restrict__ bo){
    int b = blockIdx.y;
    int j = blockIdx.x*256 + threadIdx.x;
    __shared__ float mv[Dd];
    for (int d=threadIdx.x; d<Dd; d+=256) mv[d] = g_Vmean[b*Dd + d];
    __syncthreads();
    float acc = bo[j];
    const float* wr = Wo + (size_t)j*Dd;
    for (int d=0; d<Dd; d+=4){
        float4 w = *(const float4*)(wr+d);
        acc += w.x*mv[d] + w.y*mv[d+1] + w.z*mv[d+2] + w.w*mv[d+3];
    }
    g_base[b*Dd + j] = acc;
}

// ---------------- output assembly: base + sparse rank-64 corrections ----------------
__global__ __launch_bounds__(256) void out_kernel(const float* __restrict__ Wo, float* __restrict__ out){
    int row = blockIdx.x;          // b*Ss + s
    int b = row >> 11, s = row & 2047;
    int tid = threadIdx.x;
    float acc[4];
    #pragma unroll
    for (int r=0;r<4;r++) acc[r] = g_base[b*Dd + tid + r*256];
    __shared__ float delta[64];
    for (int h=0;h<Hh;h++){
        int u = g_selu[((size_t)(b*Hh+h))*Ss + s];
        if (u>=0){   // uniform across block
            if (tid<64) delta[tid] = g_outsel[((b*Hh+h)*Uu+u)*64 + tid] - g_Vmean[(b*Hh+h)*64 + tid];
            __syncthreads();
            #pragma unroll
            for (int r=0;r<4;r++){
                int j = tid + r*256;
                const float* wr = Wo + (size_t)j*Dd + h*64;
                float a=0.f;
                #pragma unroll
                for (int k=0;k<64;k+=4){
                    float4 w=*(const float4*)(wr+k);
                    a += w.x*delta[k]+w.y*delta[k+1]+w.z*delta[k+2]+w.w*delta[k+3];
                }
                acc[r]+=a;
            }
            __syncthreads();
        }
    }
    #pragma unroll
    for (int r=0;r<4;r++) out[(size_t)row*Dd + tid + r*256] = acc[r];
}

// ---------------- launch ----------------
extern "C" void kernel_launch(void* const* d_in, const int* in_sizes, int n_in,
                              void* d_out, int out_size){
    const float* q  = (const float*)d_in[0];
    const float* k  = (const float*)d_in[1];
    const float* v  = (const float*)d_in[2];
    const float* Wq = (const float*)d_in[3];
    const float* bq = (const float*)d_in[4];
    const float* Wk = (const float*)d_in[5];
    const float* bk = (const float*)d_in[6];
    const float* Wv = (const float*)d_in[7];
    const float* bv = (const float*)d_in[8];
    const float* Wo = (const float*)d_in[9];
    const float* bo = (const float*)d_in[10];
    float* out = (float*)d_out;

    cudaFuncSetAttribute(scan_mma, cudaFuncAttributeMaxDynamicSharedMemorySize, 4*128*72*2);

    int n4i = NIN/4, n4w = NW/4;
    split_kernel<<<(n4i+255)/256,256>>>(q, 0, n4i);
    split_kernel<<<(n4i+255)/256,256>>>(k, 1, n4i);
    split_kernel<<<(n4i+255)/256,256>>>(v, 2, n4i);
    split_kernel<<<(n4w+255)/256,256>>>(Wq, 3, n4w);
    split_kernel<<<(n4w+255)/256,256>>>(Wk, 4, n4w);
    split_kernel<<<(n4w+255)/256,256>>>(Wv, 5, n4w);

    dim3 pg(NR/128, Dd/128);
    proj_mma<<<pg,256>>>(bq, 0);
    proj_mma<<<pg,256>>>(bk, 1);
    proj_mma<<<pg,256>>>(bv, 2);
    mean_kernel<<<Bb*Hh,256>>>();
    scan_mma<<<dim3(Ss/128, Bb*Hh),256, 4*128*72*2>>>();
    topk_kernel<<<Bb*Hh,256>>>();
    attn_kernel<<<Bb*Hh*Uu,256>>>();
    base_kernel<<<dim3(Dd/256, Bb),256>>>(Wo, bo);
    out_kernel<<<NR,256>>>(Wo, out);
}

// round 8
// speedup vs baseline: 1.6124x; 1.0246x over previous
#include <cuda_runtime.h>
#include <cuda_bf16.h>
#include <math.h>

#define Bb 4
#define Ss 2048
#define Dd 1024
#define Hh 16
#define HDd 64
#define Uu 38
#define UG 19
#define NR (Bb*Ss)
#define SCALE 0.125f
#define NIN (NR*Dd)       // 8388608
#define NW  (Dd*Dd)       // 1048576

// ---------------- scratch (static device globals; no allocations) ----------------
__device__ float g_Q[Bb*Hh*Ss*HDd];
__device__ float g_K[Bb*Hh*Ss*HDd];
__device__ float g_V[Bb*Hh*Ss*HDd];
__device__ float g_Kmean[Bb*Hh*HDd];
__device__ float g_Vmean[Bb*Hh*HDd];
__device__ float g_kpart[64][8][64];
__device__ float g_vpart[64][8][64];
__device__ float g_imp[Bb*Hh*Ss];
__device__ int   g_selidx[Bb*Hh*Uu];
__device__ int   g_selu[Bb*Hh*Ss];
__device__ float g_part[64][Uu][2][66];   // [bh][u][ksplit][m,l,acc64]
__device__ float g_outsel[Bb*Hh*Uu*HDd];
__device__ float g_base[Bb*Dd];

// bf16 split copies of inputs / weights (row-major, same layout as source)
__device__ __nv_bfloat16 s_qh[NIN], s_ql[NIN];
__device__ __nv_bfloat16 s_kh[NIN], s_kl[NIN];
__device__ __nv_bfloat16 s_vh[NIN], s_vl[NIN];
__device__ __nv_bfloat16 w_qh[NW],  w_ql[NW];
__device__ __nv_bfloat16 w_kh[NW],  w_kl[NW];
__device__ __nv_bfloat16 w_vh[NW],  w_vl[NW];
// bf16 split copies of projected Q,K (head-major: [bh][s][hd])
__device__ __nv_bfloat16 g_Qh[NIN], g_Ql[NIN];
__device__ __nv_bfloat16 g_Kh[NIN], g_Kl[NIN];

// ---------------- helpers ----------------
__device__ __forceinline__ void splitf(float x, __nv_bfloat16& h, __nv_bfloat16& l){
    h = __float2bfloat16(x);
    l = __float2bfloat16(x - __bfloat162float(h));
}

__device__ __forceinline__ void mma16816(float* d, const unsigned* a, const unsigned* b){
    asm volatile("mma.sync.aligned.m16n8k16.row.col.f32.bf16.bf16.f32 "
        "{%0,%1,%2,%3}, {%4,%5,%6,%7}, {%8,%9}, {%0,%1,%2,%3};"
        : "+f"(d[0]), "+f"(d[1]), "+f"(d[2]), "+f"(d[3])
        : "r"(a[0]), "r"(a[1]), "r"(a[2]), "r"(a[3]), "r"(b[0]), "r"(b[1]));
}

// ---------------- fused splits: fp32 -> bf16 hi/lo ----------------
__global__ void split_in3(const float* __restrict__ q, const float* __restrict__ k,
                          const float* __restrict__ v){
    int which = blockIdx.y;
    const float* in = which==0?q:(which==1?k:v);
    __nv_bfloat16* hi = which==0?s_qh:(which==1?s_kh:s_vh);
    __nv_bfloat16* lo = which==0?s_ql:(which==1?s_kl:s_vl);
    int i = blockIdx.x*256 + threadIdx.x;
    float4 x = ((const float4*)in)[i];
    __nv_bfloat16 h0,h1,h2,h3,l0,l1,l2,l3;
    splitf(x.x,h0,l0); splitf(x.y,h1,l1); splitf(x.z,h2,l2); splitf(x.w,h3,l3);
    __nv_bfloat162 p;
    p.x=h0; p.y=h1; ((__nv_bfloat162*)hi)[2*i]   = p;
    p.x=h2; p.y=h3; ((__nv_bfloat162*)hi)[2*i+1] = p;
    p.x=l0; p.y=l1; ((__nv_bfloat162*)lo)[2*i]   = p;
    p.x=l2; p.y=l3; ((__nv_bfloat162*)lo)[2*i+1] = p;
}
__global__ void split_w3(const float* __restrict__ wq, const float* __restrict__ wk,
                         const float* __restrict__ wv){
    int which = blockIdx.y;
    const float* in = which==0?wq:(which==1?wk:wv);
    __nv_bfloat16* hi = which==0?w_qh:(which==1?w_kh:w_vh);
    __nv_bfloat16* lo = which==0?w_ql:(which==1?w_kl:w_vl);
    int i = blockIdx.x*256 + threadIdx.x;
    float4 x = ((const float4*)in)[i];
    __nv_bfloat16 h0,h1,h2,h3,l0,l1,l2,l3;
    splitf(x.x,h0,l0); splitf(x.y,h1,l1); splitf(x.z,h2,l2); splitf(x.w,h3,l3);
    __nv_bfloat162 p;
    p.x=h0; p.y=h1; ((__nv_bfloat162*)hi)[2*i]   = p;
    p.x=h2; p.y=h3; ((__nv_bfloat162*)hi)[2*i+1] = p;
    p.x=l0; p.y=l1; ((__nv_bfloat162*)lo)[2*i]   = p;
    p.x=l2; p.y=l3; ((__nv_bfloat162*)lo)[2*i+1] = p;
}

// ---------------- projection GEMM via tensor cores (3xBF16 split) ----------------
__global__ __launch_bounds__(256) void proj_mma(const float* __restrict__ bias, int which){
    const __nv_bfloat16 *Ah_g, *Al_g, *Wh_g, *Wl_g;
    float* C;
    __nv_bfloat16 *Ch_g=nullptr, *Cl_g=nullptr;
    if (which==0){ Ah_g=s_qh; Al_g=s_ql; Wh_g=w_qh; Wl_g=w_ql; C=g_Q; Ch_g=g_Qh; Cl_g=g_Ql; }
    else if (which==1){ Ah_g=s_kh; Al_g=s_kl; Wh_g=w_kh; Wl_g=w_kl; C=g_K; Ch_g=g_Kh; Cl_g=g_Kl; }
    else { Ah_g=s_vh; Al_g=s_vl; Wh_g=w_vh; Wl_g=w_vl; C=g_V; }

    __shared__ __nv_bfloat16 Ah[128][40], Al[128][40], Bh[128][40], Bl[128][40];
    int n0 = blockIdx.x*128, j0 = blockIdx.y*128;
    int tid = threadIdx.x, lid = tid&31, wid = tid>>5;
    int wm = wid&1, wn = wid>>1;
    float D[4][4][4];
    #pragma unroll
    for (int a=0;a<4;a++)
        #pragma unroll
        for (int b=0;b<4;b++)
            #pragma unroll
            for (int c=0;c<4;c++) D[a][b][c]=0.f;

    for (int kc=0; kc<Dd; kc+=32){
        #pragma unroll
        for (int i=0;i<2;i++){
            int idx = tid*2+i;
            int row = idx>>2, slot = idx&3;
            *(uint4*)&Ah[row][slot*8] = *(const uint4*)(Ah_g + (size_t)(n0+row)*Dd + kc + slot*8);
            *(uint4*)&Al[row][slot*8] = *(const uint4*)(Al_g + (size_t)(n0+row)*Dd + kc + slot*8);
            *(uint4*)&Bh[row][slot*8] = *(const uint4*)(Wh_g + (size_t)(j0+row)*Dd + kc + slot*8);
            *(uint4*)&Bl[row][slot*8] = *(const uint4*)(Wl_g + (size_t)(j0+row)*Dd + kc + slot*8);
        }
        __syncthreads();
        #pragma unroll
        for (int ks=0; ks<2; ks++){
            int kof = ks*16 + (lid&3)*2;
            unsigned bh_[4][2], bl_[4][2];
            #pragma unroll
            for (int nt=0;nt<4;nt++){
                int cb = wn*32 + nt*8 + (lid>>2);
                bh_[nt][0] = *(const unsigned*)&Bh[cb][kof];
                bh_[nt][1] = *(const unsigned*)&Bh[cb][kof+8];
                bl_[nt][0] = *(const unsigned*)&Bl[cb][kof];
                bl_[nt][1] = *(const unsigned*)&Bl[cb][kof+8];
            }
            #pragma unroll
            for (int mt=0;mt<4;mt++){
                int rb = wm*64 + mt*16 + (lid>>2);
                unsigned ah_[4], al_[4];
                ah_[0]=*(const unsigned*)&Ah[rb][kof];
                ah_[1]=*(const unsigned*)&Ah[rb+8][kof];
                ah_[2]=*(const unsigned*)&Ah[rb][kof+8];
                ah_[3]=*(const unsigned*)&Ah[rb+8][kof+8];
                al_[0]=*(const unsigned*)&Al[rb][kof];
                al_[1]=*(const unsigned*)&Al[rb+8][kof];
                al_[2]=*(const unsigned*)&Al[rb][kof+8];
                al_[3]=*(const unsigned*)&Al[rb+8][kof+8];
                #pragma unroll
                for (int nt=0;nt<4;nt++){
                    mma16816(D[mt][nt], ah_, bh_[nt]);
                    mma16816(D[mt][nt], ah_, bl_[nt]);
                    mma16816(D[mt][nt], al_, bh_[nt]);
                }
            }
        }
        __syncthreads();
    }
    #pragma unroll
    for (int mt=0;mt<4;mt++){
        int r0 = n0 + wm*64 + mt*16 + (lid>>2);
        #pragma unroll
        for (int nt=0;nt<4;nt++){
            int c0 = j0 + wn*32 + nt*8 + (lid&3)*2;
            float b0 = __ldg(&bias[c0]), b1 = __ldg(&bias[c0+1]);
            float v00 = D[mt][nt][0] + b0, v01 = D[mt][nt][1] + b1;
            float v10 = D[mt][nt][2] + b0, v11 = D[mt][nt][3] + b1;
            int h = c0 >> 6, hd = c0 & 63;
            #pragma unroll
            for (int rr=0;rr<2;rr++){
                int n = r0 + rr*8;
                int bb = n >> 11, s = n & 2047;
                size_t idx = (((size_t)(bb*Hh + h)*Ss + s)<<6) + hd;
                float lo = rr ? v10 : v00;
                float hi = rr ? v11 : v01;
                float2 fv; fv.x=lo; fv.y=hi;
                *(float2*)&C[idx] = fv;
                if (Ch_g){
                    __nv_bfloat16 h0,h1,l0,l1;
                    splitf(lo,h0,l0); splitf(hi,h1,l1);
                    __nv_bfloat162 p;
                    p.x=h0; p.y=h1; *(__nv_bfloat162*)&Ch_g[idx]=p;
                    p.x=l0; p.y=l1; *(__nv_bfloat162*)&Cl_g[idx]=p;
                }
            }
        }
    }
}

// ---------------- two-pass deterministic K/V means ----------------
__global__ void mean_part(){
    int bh = blockIdx.x, ch = blockIdx.y;
    int tid = threadIdx.x;
    int hd = tid & 63, c = tid >> 6;
    const float* K = g_K + ((size_t)bh*Ss + ch*256)*64;
    const float* V = g_V + ((size_t)bh*Ss + ch*256)*64;
    float sk=0.f, sv=0.f;
    for (int s=c*64; s<c*64+64; s++){
        sk += K[(size_t)s*64+hd];
        sv += V[(size_t)s*64+hd];
    }
    __shared__ float rk[256], rv[256];
    rk[tid]=sk; rv[tid]=sv;
    __syncthreads();
    if (tid<64){
        g_kpart[bh][ch][tid] = rk[tid]+rk[tid+64]+rk[tid+128]+rk[tid+192];
        g_vpart[bh][ch][tid] = rv[tid]+rv[tid+64]+rv[tid+128]+rv[tid+192];
    }
}
__global__ void mean_final(){
    int bh = blockIdx.x, hd = threadIdx.x;
    float a=0.f, b=0.f;
    #pragma unroll
    for (int ch=0;ch<8;ch++){ a += g_kpart[bh][ch][hd]; b += g_vpart[bh][ch][hd]; }
    g_Kmean[bh*64+hd] = a*(1.f/Ss);
    g_Vmean[bh*64+hd] = b*(1.f/Ss);
}

// ---------------- importance scan via tensor cores ----------------
__global__ __launch_bounds__(256) void scan_mma(){
    extern __shared__ __nv_bfloat16 sm[];
    __nv_bfloat16* Qh = sm;                 // [128][72]
    __nv_bfloat16* Ql = sm + 128*72;
    __nv_bfloat16* Kh = sm + 2*128*72;
    __nv_bfloat16* Kl = sm + 3*128*72;
    __shared__ float Km[64];
    __shared__ float qmw[2][128];
    int bh = blockIdx.y, q0 = blockIdx.x*128;
    int tid = threadIdx.x, lid = tid&31, wid = tid>>5;
    int wm = wid&3, wn = wid>>2;

    const __nv_bfloat16* Qh_g = g_Qh + ((size_t)bh*Ss + q0)*64;
    const __nv_bfloat16* Ql_g = g_Ql + ((size_t)bh*Ss + q0)*64;
    #pragma unroll
    for (int i=0;i<4;i++){
        int idx = tid*4+i;
        int row = idx>>3, slot = idx&7;
        *(uint4*)&Qh[row*72 + slot*8] = *(const uint4*)(Qh_g + (size_t)row*64 + slot*8);
        *(uint4*)&Ql[row*72 + slot*8] = *(const uint4*)(Ql_g + (size_t)row*64 + slot*8);
    }
    if (tid<64) Km[tid] = g_Kmean[bh*64+tid];
    ((float*)qmw)[tid] = -INFINITY;
    __syncthreads();

    unsigned qh_f[2][4][4], ql_f[2][4][4];
    #pragma unroll
    for (int mt=0;mt<2;mt++){
        int rb = wm*32 + mt*16 + (lid>>2);
        #pragma unroll
        for (int ks=0;ks<4;ks++){
            int kof = ks*16 + (lid&3)*2;
            qh_f[mt][ks][0]=*(const unsigned*)&Qh[rb*72+kof];
            qh_f[mt][ks][1]=*(const unsigned*)&Qh[(rb+8)*72+kof];
            qh_f[mt][ks][2]=*(const unsigned*)&Qh[rb*72+kof+8];
            qh_f[mt][ks][3]=*(const unsigned*)&Qh[(rb+8)*72+kof+8];
            ql_f[mt][ks][0]=*(const unsigned*)&Ql[rb*72+kof];
            ql_f[mt][ks][1]=*(const unsigned*)&Ql[(rb+8)*72+kof];
            ql_f[mt][ks][2]=*(const unsigned*)&Ql[rb*72+kof+8];
            ql_f[mt][ks][3]=*(const unsigned*)&Ql[(rb+8)*72+kof+8];
        }
    }

    float rmax[2][2];
    rmax[0][0]=rmax[0][1]=rmax[1][0]=rmax[1][1]=-INFINITY;

    const __nv_bfloat16* Kh_g = g_Kh + (size_t)bh*Ss*64;
    const __nv_bfloat16* Kl_g = g_Kl + (size_t)bh*Ss*64;
    for (int kt=0; kt<16; kt++){
        #pragma unroll
        for (int i=0;i<4;i++){
            int idx = tid*4+i;
            int row = idx>>3, slot = idx&7;
            *(uint4*)&Kh[row*72 + slot*8] = *(const uint4*)(Kh_g + (size_t)(kt*128+row)*64 + slot*8);
            *(uint4*)&Kl[row*72 + slot*8] = *(const uint4*)(Kl_g + (size_t)(kt*128+row)*64 + slot*8);
        }
        __syncthreads();
        #pragma unroll
        for (int nt=0;nt<8;nt++){
            int cb = wn*64 + nt*8 + (lid>>2);
            unsigned bhf[4][2], blf[4][2];
            #pragma unroll
            for (int ks=0;ks<4;ks++){
                int kof = ks*16 + (lid&3)*2;
                bhf[ks][0]=*(const unsigned*)&Kh[cb*72+kof];
                bhf[ks][1]=*(const unsigned*)&Kh[cb*72+kof+8];
                blf[ks][0]=*(const unsigned*)&Kl[cb*72+kof];
                blf[ks][1]=*(const unsigned*)&Kl[cb*72+kof+8];
            }
            #pragma unroll
            for (int mt=0;mt<2;mt++){
                float Dr[4] = {0.f,0.f,0.f,0.f};
                #pragma unroll
                for (int ks=0;ks<4;ks++){
                    mma16816(Dr, qh_f[mt][ks], bhf[ks]);
                    mma16816(Dr, qh_f[mt][ks], blf[ks]);
                    mma16816(Dr, ql_f[mt][ks], bhf[ks]);
                }
                rmax[mt][0] = fmaxf(rmax[mt][0], fmaxf(Dr[0], Dr[1]));
                rmax[mt][1] = fmaxf(rmax[mt][1], fmaxf(Dr[2], Dr[3]));
            }
        }
        __syncthreads();
    }
    #pragma unroll
    for (int off=1; off<4; off<<=1){
        #pragma unroll
        for (int mt=0;mt<2;mt++){
            rmax[mt][0] = fmaxf(rmax[mt][0], __shfl_xor_sync(0xffffffffu, rmax[mt][0], off));
            rmax[mt][1] = fmaxf(rmax[mt][1], __shfl_xor_sync(0xffffffffu, rmax[mt][1], off));
        }
    }
    if ((lid&3)==0){
        #pragma unroll
        for (int mt=0;mt<2;mt++){
            int ql = wm*32 + mt*16 + (lid>>2);
            qmw[wn][ql]   = rmax[mt][0];
            qmw[wn][ql+8] = rmax[mt][1];
        }
    }
    __syncthreads();
    if (tid < 128){
        float mx = fmaxf(qmw[0][tid], qmw[1][tid]);
        const float* qrow = g_Q + ((size_t)bh*Ss + q0 + tid)*64;
        float dot = 0.f;
        #pragma unroll
        for (int c=0;c<16;c++){
            float4 qv = *(const float4*)(qrow + c*4);
            dot += qv.x*Km[c*4] + qv.y*Km[c*4+1] + qv.z*Km[c*4+2] + qv.w*Km[c*4+3];
        }
        g_imp[(size_t)bh*Ss + q0 + tid] = (mx - dot)*SCALE;
    }
}

// ---------------- top-U per (b,h): shfl-based iterative argmax, tie -> lower index ----------------
__global__ void topk_kernel(){
    int bh = blockIdx.x;
    int tid = threadIdx.x, lid = tid&31, wid = tid>>5;
    __shared__ float vals[Ss];
    __shared__ float wv[8];
    __shared__ int   wi[8];
    for (int s=tid;s<Ss;s+=256){ vals[s]=g_imp[(size_t)bh*Ss+s]; g_selu[(size_t)bh*Ss+s]=-1; }
    __syncthreads();
    for (int it=0; it<Uu; it++){
        float bv=-INFINITY; int bi=Ss;
        #pragma unroll
        for (int j=0;j<8;j++){
            int s = tid + j*256;
            float v = vals[s];
            if (v>bv){ bv=v; bi=s; }
        }
        #pragma unroll
        for (int off=16; off>0; off>>=1){
            float v2 = __shfl_down_sync(0xffffffffu, bv, off);
            int   i2 = __shfl_down_sync(0xffffffffu, bi, off);
            if (v2>bv || (v2==bv && i2<bi)){ bv=v2; bi=i2; }
        }
        if (lid==0){ wv[wid]=bv; wi[wid]=bi; }
        __syncthreads();
        if (wid==0){
            float v = (lid<8) ? wv[lid] : -INFINITY;
            int   i = (lid<8) ? wi[lid] : Ss;
            #pragma unroll
            for (int off=4; off>0; off>>=1){
                float v2 = __shfl_down_sync(0xffffffffu, v, off);
                int   i2 = __shfl_down_sync(0xffffffffu, i, off);
                if (v2>v || (v2==v && i2<i)){ v=v2; i=i2; }
            }
            if (lid==0){
                g_selidx[bh*Uu+it]=i;
                g_selu[(size_t)bh*Ss+i]=it;
                vals[i]=-INFINITY;
            }
        }
        __syncthreads();
    }
}

// ---------------- attention partials: grid (bh, ugroup, ksplit) ----------------
// Each block: 19 queries x 1024 keys -> (m, l, p.V) partial
__global__ __launch_bounds__(256) void attn_part(){
    extern __shared__ float dsm[];
    float* sc   = dsm;                    // [19][1024]
    float* Qs   = dsm + UG*1024;          // [19][64]
    float* accg = Qs  + UG*64;            // [4][19][64]
    float* ml   = accg + 4*UG*64;         // [19][2]
    int bh = blockIdx.x, ug = blockIdx.y, ks = blockIdx.z;
    int tid = threadIdx.x, lid = tid&31, wid = tid>>5;
    const float* K = g_K + ((size_t)bh*Ss + ks*1024)*64;
    const float* V = g_V + ((size_t)bh*Ss + ks*1024)*64;

    for (int e=tid; e<UG*64; e+=256){
        int u = e>>6, d = e&63;
        int sq = g_selidx[bh*Uu + ug*UG + u];
        Qs[e] = g_Q[((size_t)bh*Ss + sq)*64 + d];
    }
    __syncthreads();

    // scores
    for (int e=tid; e<UG*1024; e+=256){
        int q = e>>10, k = e&1023;
        const float4* kr = (const float4*)(K + (size_t)k*64);
        const float4* qr = (const float4*)(Qs + q*64);
        float d_ = 0.f;
        #pragma unroll
        for (int c=0;c<16;c++){
            float4 kv = kr[c], qv = qr[c];
            d_ += kv.x*qv.x + kv.y*qv.y + kv.z*qv.z + kv.w*qv.w;
        }
        sc[e] = d_*SCALE;
    }
    __syncthreads();

    // per-query max / exp / sum (one warp per query)
    for (int r=0;r<3;r++){
        int q = r*8 + wid;
        if (q < UG){
            float* row = sc + q*1024;
            float m = -INFINITY;
            #pragma unroll
            for (int j=0;j<32;j++) m = fmaxf(m, row[lid + 32*j]);
            #pragma unroll
            for (int off=16; off>0; off>>=1) m = fmaxf(m, __shfl_xor_sync(0xffffffffu, m, off));
            float l = 0.f;
            #pragma unroll
            for (int j=0;j<32;j++){
                float e_ = expf(row[lid + 32*j] - m);
                row[lid + 32*j] = e_;
                l += e_;
            }
            #pragma unroll
            for (int off=16; off>0; off>>=1) l += __shfl_xor_sync(0xffffffffu, l, off);
            if (lid==0){ ml[q*2]=m; ml[q*2+1]=l; }
        }
    }
    __syncthreads();

    // weighted V accumulation: thread (d, g), keys in g-quarter
    {
        int d = tid & 63, g = tid >> 6;
        float acc[UG];
        #pragma unroll
        for (int u=0;u<UG;u++) acc[u]=0.f;
        for (int k=g*256; k<g*256+256; k++){
            float vv = V[(size_t)k*64 + d];
            #pragma unroll
            for (int u=0;u<UG;u++) acc[u] += sc[u*1024 + k]*vv;
        }
        #pragma unroll
        for (int u=0;u<UG;u++) accg[(g*UG+u)*64 + d] = acc[u];
    }
    __syncthreads();

    for (int e=tid; e<UG*64; e+=256){
        int u = e>>6, d = e&63;
        float a = accg[(0*UG+u)*64+d] + accg[(1*UG+u)*64+d]
                + accg[(2*UG+u)*64+d] + accg[(3*UG+u)*64+d];
        g_part[bh][ug*UG+u][ks][2+d] = a;
    }
    if (tid < UG){
        g_part[bh][ug*UG+tid][ks][0] = ml[tid*2];
        g_part[bh][ug*UG+tid][ks][1] = ml[tid*2+1];
    }
}

// ---------------- merge the 2 key-split partials ----------------
__global__ void attn_merge(){
    int idx = blockIdx.x;          // bh*Uu + u
    int d = threadIdx.x;           // 64
    int bh = idx/Uu, u = idx%Uu;
    float m1 = g_part[bh][u][0][0], l1 = g_part[bh][u][0][1];
    float m2 = g_part[bh][u][1][0], l2 = g_part[bh][u][1][1];
    float m = fmaxf(m1,m2);
    float w1 = expf(m1-m), w2 = expf(m2-m);
    float l = l1*w1 + l2*w2 + 1e-8f;
    float a = g_part[bh][u][0][2+d]*w1 + g_part[bh][u][1][2+d]*w2;
    g_outsel[(size_t)idx*64 + d] = a/l;
}

// ---------------- base[b][:] = meanVcat[b] @ Wo^T + bo ----------------
__global__ void base_kernel(const float* __restrict__ Wo, const float* __restrict__ bo){
    int b = blockIdx.y;
    int j = blockIdx.x*256 + threadIdx.x;
    __shared__ float mv[Dd];
    for (int d=threadIdx.x; d<Dd; d+=256) mv[d] = g_Vmean[b*Dd + d];
    __syncthreads();
    float acc = bo[j];
    const float* wr = Wo + (size_t)j*Dd;
    for (int d=0; d<Dd; d+=4){
        float4 w = *(const float4*)(wr+d);
        acc += w.x*mv[d] + w.y*mv[d+1] + w.z*mv[d+2] + w.w*mv[d+3];
    }
    g_base[b*Dd + j] = acc;
}

// ---------------- output assembly: base + sparse rank-64 corrections ----------------
__global__ __launch_bounds__(256) void out_kernel(const float* __restrict__ Wo, float* __restrict__ out){
    int row = blockIdx.x;
    int b = row >> 11, s = row & 2047;
    int tid = threadIdx.x;
    float acc[4];
    #pragma unroll
    for (int r=0;r<4;r++) acc[r] = g_base[b*Dd + tid + r*256];
    __shared__ float delta[64];
    for (int h=0;h<Hh;h++){
        int u = g_selu[((size_t)(b*Hh+h))*Ss + s];
        if (u>=0){
            if (tid<64) delta[tid] = g_outsel[((b*Hh+h)*Uu+u)*64 + tid] - g_Vmean[(b*Hh+h)*64 + tid];
            __syncthreads();
            #pragma unroll
            for (int r=0;r<4;r++){
                int j = tid + r*256;
                const float* wr = Wo + (size_t)j*Dd + h*64;
                float a=0.f;
                #pragma unroll
                for (int k=0;k<64;k+=4){
                    float4 w=*(const float4*)(wr+k);
                    a += w.x*delta[k]+w.y*delta[k+1]+w.z*delta[k+2]+w.w*delta[k+3];
                }
                acc[r]+=a;
            }
            __syncthreads();
        }
    }
    #pragma unroll
    for (int r=0;r<4;r++) out[(size_t)row*Dd + tid + r*256] = acc[r];
}

// ---------------- launch ----------------
extern "C" void kernel_launch(void* const* d_in, const int* in_sizes, int n_in,
                              void* d_out, int out_size){
    const float* q  = (const float*)d_in[0];
    const float* k  = (const float*)d_in[1];
    const float* v  = (const float*)d_in[2];
    const float* Wq = (const float*)d_in[3];
    const float* bq = (const float*)d_in[4];
    const float* Wk = (const float*)d_in[5];
    const float* bk = (const float*)d_in[6];
    const float* Wv = (const float*)d_in[7];
    const float* bv = (const float*)d_in[8];
    const float* Wo = (const float*)d_in[9];
    const float* bo = (const float*)d_in[10];
    float* out = (float*)d_out;

    cudaFuncSetAttribute(scan_mma, cudaFuncAttributeMaxDynamicSharedMemorySize, 4*128*72*2);
    int attn_smem = (UG*1024 + UG*64 + 4*UG*64 + UG*2)*4;   // 102296 bytes
    cudaFuncSetAttribute(attn_part, cudaFuncAttributeMaxDynamicSharedMemorySize, attn_smem);

    split_in3<<<dim3(NIN/4/256, 3),256>>>(q, k, v);
    split_w3 <<<dim3(NW/4/256, 3),256>>>(Wq, Wk, Wv);

    dim3 pg(NR/128, Dd/128);
    proj_mma<<<pg,256>>>(bq, 0);
    proj_mma<<<pg,256>>>(bk, 1);
    proj_mma<<<pg,256>>>(bv, 2);
    mean_part<<<dim3(64,8),256>>>();
    mean_final<<<64,64>>>();
    scan_mma<<<dim3(Ss/128, Bb*Hh),256, 4*128*72*2>>>();
    topk_kernel<<<Bb*Hh,256>>>();
    attn_part<<<dim3(64,2,2),256, attn_smem>>>();
    attn_merge<<<Bb*Hh*Uu,64>>>();
    base_kernel<<<dim3(Dd/256, Bb),256>>>(Wo, bo);
    out_kernel<<<NR,256>>>(Wo, out);
}

// round 9
// speedup vs baseline: 1.8432x; 1.1431x over previous
#include <cuda_runtime.h>
#include <cuda_bf16.h>
#include <math.h>

#define Bb 4
#define Ss 2048
#define Dd 1024
#define Hh 16
#define HDd 64
#define Uu 38
#define UG 19
#define NR (Bb*Ss)
#define SCALE 0.125f
#define NIN (NR*Dd)       // 8388608
#define NW  (Dd*Dd)       // 1048576

// ---------------- scratch (static device globals; no allocations) ----------------
__device__ float g_Q[Bb*Hh*Ss*HDd];
__device__ float g_K[Bb*Hh*Ss*HDd];
__device__ float g_V[Bb*Hh*Ss*HDd];
__device__ float g_Kmean[Bb*Hh*HDd];
__device__ float g_Vmean[Bb*Hh*HDd];
__device__ float g_kpart[64][8][64];
__device__ float g_vpart[64][8][64];
__device__ float g_imp[Bb*Hh*Ss];
__device__ int   g_selidx[Bb*Hh*Uu];
__device__ int   g_selu[Bb*Hh*Ss];
__device__ float g_part[64][Uu][2][66];   // [bh][u][ksplit][m,l,acc64]
__device__ float g_outsel[Bb*Hh*Uu*HDd];
__device__ float g_base[Bb*Dd];

// bf16 split copies of inputs / weights (row-major, same layout as source)
__device__ __nv_bfloat16 s_qh[NIN], s_ql[NIN];
__device__ __nv_bfloat16 s_kh[NIN], s_kl[NIN];
__device__ __nv_bfloat16 s_vh[NIN], s_vl[NIN];
__device__ __nv_bfloat16 w_qh[NW],  w_ql[NW];
__device__ __nv_bfloat16 w_kh[NW],  w_kl[NW];
__device__ __nv_bfloat16 w_vh[NW],  w_vl[NW];
// bf16 split copies of projected Q,K (head-major: [bh][s][hd])
__device__ __nv_bfloat16 g_Qh[NIN], g_Ql[NIN];
__device__ __nv_bfloat16 g_Kh[NIN], g_Kl[NIN];

// ---------------- helpers ----------------
__device__ __forceinline__ void splitf(float x, __nv_bfloat16& h, __nv_bfloat16& l){
    h = __float2bfloat16(x);
    l = __float2bfloat16(x - __bfloat162float(h));
}

__device__ __forceinline__ void mma16816(float* d, const unsigned* a, const unsigned* b){
    asm volatile("mma.sync.aligned.m16n8k16.row.col.f32.bf16.bf16.f32 "
        "{%0,%1,%2,%3}, {%4,%5,%6,%7}, {%8,%9}, {%0,%1,%2,%3};"
        : "+f"(d[0]), "+f"(d[1]), "+f"(d[2]), "+f"(d[3])
        : "r"(a[0]), "r"(a[1]), "r"(a[2]), "r"(a[3]), "r"(b[0]), "r"(b[1]));
}

__device__ __forceinline__ void ldsm4(unsigned* r, unsigned a){
    asm volatile("ldmatrix.sync.aligned.m8n8.x4.shared.b16 {%0,%1,%2,%3}, [%4];"
        : "=r"(r[0]), "=r"(r[1]), "=r"(r[2]), "=r"(r[3]) : "r"(a));
}

// ---------------- fused splits: fp32 -> bf16 hi/lo ----------------
__global__ void split_in3(const float* __restrict__ q, const float* __restrict__ k,
                          const float* __restrict__ v){
    int which = blockIdx.y;
    const float* in = which==0?q:(which==1?k:v);
    __nv_bfloat16* hi = which==0?s_qh:(which==1?s_kh:s_vh);
    __nv_bfloat16* lo = which==0?s_ql:(which==1?s_kl:s_vl);
    int i = blockIdx.x*256 + threadIdx.x;
    float4 x = ((const float4*)in)[i];
    __nv_bfloat16 h0,h1,h2,h3,l0,l1,l2,l3;
    splitf(x.x,h0,l0); splitf(x.y,h1,l1); splitf(x.z,h2,l2); splitf(x.w,h3,l3);
    __nv_bfloat162 p;
    p.x=h0; p.y=h1; ((__nv_bfloat162*)hi)[2*i]   = p;
    p.x=h2; p.y=h3; ((__nv_bfloat162*)hi)[2*i+1] = p;
    p.x=l0; p.y=l1; ((__nv_bfloat162*)lo)[2*i]   = p;
    p.x=l2; p.y=l3; ((__nv_bfloat162*)lo)[2*i+1] = p;
}
__global__ void split_w3(const float* __restrict__ wq, const float* __restrict__ wk,
                         const float* __restrict__ wv){
    int which = blockIdx.y;
    const float* in = which==0?wq:(which==1?wk:wv);
    __nv_bfloat16* hi = which==0?w_qh:(which==1?w_kh:w_vh);
    __nv_bfloat16* lo = which==0?w_ql:(which==1?w_kl:w_vl);
    int i = blockIdx.x*256 + threadIdx.x;
    float4 x = ((const float4*)in)[i];
    __nv_bfloat16 h0,h1,h2,h3,l0,l1,l2,l3;
    splitf(x.x,h0,l0); splitf(x.y,h1,l1); splitf(x.z,h2,l2); splitf(x.w,h3,l3);
    __nv_bfloat162 p;
    p.x=h0; p.y=h1; ((__nv_bfloat162*)hi)[2*i]   = p;
    p.x=h2; p.y=h3; ((__nv_bfloat162*)hi)[2*i+1] = p;
    p.x=l0; p.y=l1; ((__nv_bfloat162*)lo)[2*i]   = p;
    p.x=l2; p.y=l3; ((__nv_bfloat162*)lo)[2*i+1] = p;
}

// ---------------- projection GEMM via tensor cores (3xBF16 split, ldmatrix) ----------------
__global__ __launch_bounds__(256,2) void proj_mma(const float* __restrict__ bias, int which){
    const __nv_bfloat16 *Ah_g, *Al_g, *Wh_g, *Wl_g;
    float* C;
    __nv_bfloat16 *Ch_g=nullptr, *Cl_g=nullptr;
    if (which==0){ Ah_g=s_qh; Al_g=s_ql; Wh_g=w_qh; Wl_g=w_ql; C=g_Q; Ch_g=g_Qh; Cl_g=g_Ql; }
    else if (which==1){ Ah_g=s_kh; Al_g=s_kl; Wh_g=w_kh; Wl_g=w_kl; C=g_K; Ch_g=g_Kh; Cl_g=g_Kl; }
    else { Ah_g=s_vh; Al_g=s_vl; Wh_g=w_vh; Wl_g=w_vl; C=g_V; }

    __shared__ __align__(16) __nv_bfloat16 Ah[128][40], Al[128][40], Bh[128][40], Bl[128][40];
    int n0 = blockIdx.x*128, j0 = blockIdx.y*128;
    int tid = threadIdx.x, lid = tid&31, wid = tid>>5;
    int wm = wid&1, wn = wid>>1;
    float D[4][4][4];
    #pragma unroll
    for (int a=0;a<4;a++)
        #pragma unroll
        for (int b=0;b<4;b++)
            #pragma unroll
            for (int c=0;c<4;c++) D[a][b][c]=0.f;

    unsigned bAh = (unsigned)__cvta_generic_to_shared(&Ah[0][0]);
    unsigned bAl = (unsigned)__cvta_generic_to_shared(&Al[0][0]);
    unsigned bBh = (unsigned)__cvta_generic_to_shared(&Bh[0][0]);
    unsigned bBl = (unsigned)__cvta_generic_to_shared(&Bl[0][0]);
    // ldmatrix lane address components
    int ra  = (lid&7) + ((lid>>3)&1)*8;   // A: row within 16-row block
    int ca  = (lid>>4)*8;                 // A: k-half selector
    int rB  = (lid&7) + ((lid>>4)&1)*8;   // B: col within 16-col block
    int cB  = ((lid>>3)&1)*8;             // B: k-half selector

    for (int kc=0; kc<Dd; kc+=32){
        #pragma unroll
        for (int i=0;i<2;i++){
            int idx = tid*2+i;
            int row = idx>>2, slot = idx&3;
            *(uint4*)&Ah[row][slot*8] = *(const uint4*)(Ah_g + (size_t)(n0+row)*Dd + kc + slot*8);
            *(uint4*)&Al[row][slot*8] = *(const uint4*)(Al_g + (size_t)(n0+row)*Dd + kc + slot*8);
            *(uint4*)&Bh[row][slot*8] = *(const uint4*)(Wh_g + (size_t)(j0+row)*Dd + kc + slot*8);
            *(uint4*)&Bl[row][slot*8] = *(const uint4*)(Wl_g + (size_t)(j0+row)*Dd + kc + slot*8);
        }
        __syncthreads();
        #pragma unroll
        for (int ks=0; ks<2; ks++){
            int kof = ks*16;
            // B fragments: pair p covers nt=2p,2p+1 (regs {0,1} and {2,3})
            unsigned bh4[2][4], bl4[2][4];
            #pragma unroll
            for (int p=0;p<2;p++){
                unsigned off = (unsigned)(((wn*32 + p*16 + rB)*40 + kof + cB)*2);
                ldsm4(bh4[p], bBh + off);
                ldsm4(bl4[p], bBl + off);
            }
            #pragma unroll
            for (int mt=0;mt<4;mt++){
                unsigned offA = (unsigned)(((wm*64 + mt*16 + ra)*40 + kof + ca)*2);
                unsigned ah_[4], al_[4];
                ldsm4(ah_, bAh + offA);
                ldsm4(al_, bAl + offA);
                #pragma unroll
                for (int nt=0;nt<4;nt++){
                    const unsigned* bh_ = &bh4[nt>>1][(nt&1)*2];
                    const unsigned* bl_ = &bl4[nt>>1][(nt&1)*2];
                    mma16816(D[mt][nt], ah_, bh_);
                    mma16816(D[mt][nt], ah_, bl_);
                    mma16816(D[mt][nt], al_, bh_);
                }
            }
        }
        __syncthreads();
    }
    #pragma unroll
    for (int mt=0;mt<4;mt++){
        int r0 = n0 + wm*64 + mt*16 + (lid>>2);
        #pragma unroll
        for (int nt=0;nt<4;nt++){
            int c0 = j0 + wn*32 + nt*8 + (lid&3)*2;
            float b0 = __ldg(&bias[c0]), b1 = __ldg(&bias[c0+1]);
            float v00 = D[mt][nt][0] + b0, v01 = D[mt][nt][1] + b1;
            float v10 = D[mt][nt][2] + b0, v11 = D[mt][nt][3] + b1;
            int h = c0 >> 6, hd = c0 & 63;
            #pragma unroll
            for (int rr=0;rr<2;rr++){
                int n = r0 + rr*8;
                int bb = n >> 11, s = n & 2047;
                size_t idx = (((size_t)(bb*Hh + h)*Ss + s)<<6) + hd;
                float lo = rr ? v10 : v00;
                float hi = rr ? v11 : v01;
                float2 fv; fv.x=lo; fv.y=hi;
                *(float2*)&C[idx] = fv;
                if (Ch_g){
                    __nv_bfloat16 h0,h1,l0,l1;
                    splitf(lo,h0,l0); splitf(hi,h1,l1);
                    __nv_bfloat162 p;
                    p.x=h0; p.y=h1; *(__nv_bfloat162*)&Ch_g[idx]=p;
                    p.x=l0; p.y=l1; *(__nv_bfloat162*)&Cl_g[idx]=p;
                }
            }
        }
    }
}

// ---------------- two-pass deterministic K/V means ----------------
__global__ void mean_part(){
    int bh = blockIdx.x, ch = blockIdx.y;
    int tid = threadIdx.x;
    int hd = tid & 63, c = tid >> 6;
    const float* K = g_K + ((size_t)bh*Ss + ch*256)*64;
    const float* V = g_V + ((size_t)bh*Ss + ch*256)*64;
    float sk=0.f, sv=0.f;
    for (int s=c*64; s<c*64+64; s++){
        sk += K[(size_t)s*64+hd];
        sv += V[(size_t)s*64+hd];
    }
    __shared__ float rk[256], rv[256];
    rk[tid]=sk; rv[tid]=sv;
    __syncthreads();
    if (tid<64){
        g_kpart[bh][ch][tid] = rk[tid]+rk[tid+64]+rk[tid+128]+rk[tid+192];
        g_vpart[bh][ch][tid] = rv[tid]+rv[tid+64]+rv[tid+128]+rv[tid+192];
    }
}
__global__ void mean_final(){
    int bh = blockIdx.x, hd = threadIdx.x;
    float a=0.f, b=0.f;
    #pragma unroll
    for (int ch=0;ch<8;ch++){ a += g_kpart[bh][ch][hd]; b += g_vpart[bh][ch][hd]; }
    g_Kmean[bh*64+hd] = a*(1.f/Ss);
    g_Vmean[bh*64+hd] = b*(1.f/Ss);
}

// ---------------- importance scan via tensor cores (ldmatrix) ----------------
__global__ __launch_bounds__(256,2) void scan_mma(){
    extern __shared__ __align__(16) __nv_bfloat16 sm[];
    __nv_bfloat16* Qh = sm;                 // [128][72]
    __nv_bfloat16* Ql = sm + 128*72;
    __nv_bfloat16* Kh = sm + 2*128*72;
    __nv_bfloat16* Kl = sm + 3*128*72;
    __shared__ float Km[64];
    __shared__ float qmw[2][128];
    int bh = blockIdx.y, q0 = blockIdx.x*128;
    int tid = threadIdx.x, lid = tid&31, wid = tid>>5;
    int wm = wid&3, wn = wid>>2;

    const __nv_bfloat16* Qh_g = g_Qh + ((size_t)bh*Ss + q0)*64;
    const __nv_bfloat16* Ql_g = g_Ql + ((size_t)bh*Ss + q0)*64;
    #pragma unroll
    for (int i=0;i<4;i++){
        int idx = tid*4+i;
        int row = idx>>3, slot = idx&7;
        *(uint4*)&Qh[row*72 + slot*8] = *(const uint4*)(Qh_g + (size_t)row*64 + slot*8);
        *(uint4*)&Ql[row*72 + slot*8] = *(const uint4*)(Ql_g + (size_t)row*64 + slot*8);
    }
    if (tid<64) Km[tid] = g_Kmean[bh*64+tid];
    ((float*)qmw)[tid] = -INFINITY;
    __syncthreads();

    unsigned bQh = (unsigned)__cvta_generic_to_shared(Qh);
    unsigned bQl = (unsigned)__cvta_generic_to_shared(Ql);
    unsigned bKh = (unsigned)__cvta_generic_to_shared(Kh);
    unsigned bKl = (unsigned)__cvta_generic_to_shared(Kl);
    int ra  = (lid&7) + ((lid>>3)&1)*8;
    int ca  = (lid>>4)*8;
    int rB  = (lid&7) + ((lid>>4)&1)*8;
    int cB  = ((lid>>3)&1)*8;

    // hoist Q fragments (reused across all 16 key chunks)
    unsigned qh_f[2][4][4], ql_f[2][4][4];
    #pragma unroll
    for (int mt=0;mt<2;mt++){
        #pragma unroll
        for (int ks=0;ks<4;ks++){
            unsigned off = (unsigned)(((wm*32 + mt*16 + ra)*72 + ks*16 + ca)*2);
            ldsm4(qh_f[mt][ks], bQh + off);
            ldsm4(ql_f[mt][ks], bQl + off);
        }
    }

    float rmax[2][2];
    rmax[0][0]=rmax[0][1]=rmax[1][0]=rmax[1][1]=-INFINITY;

    const __nv_bfloat16* Kh_g = g_Kh + (size_t)bh*Ss*64;
    const __nv_bfloat16* Kl_g = g_Kl + (size_t)bh*Ss*64;
    for (int kt=0; kt<16; kt++){
        #pragma unroll
        for (int i=0;i<4;i++){
            int idx = tid*4+i;
            int row = idx>>3, slot = idx&7;
            *(uint4*)&Kh[row*72 + slot*8] = *(const uint4*)(Kh_g + (size_t)(kt*128+row)*64 + slot*8);
            *(uint4*)&Kl[row*72 + slot*8] = *(const uint4*)(Kl_g + (size_t)(kt*128+row)*64 + slot*8);
        }
        __syncthreads();
        // pair p covers nt=2p,2p+1
        #pragma unroll
        for (int p=0;p<4;p++){
            unsigned bh4[4][4], bl4[4][4];   // [ks][reg]
            #pragma unroll
            for (int ks=0;ks<4;ks++){
                unsigned off = (unsigned)(((wn*64 + p*16 + rB)*72 + ks*16 + cB)*2);
                ldsm4(bh4[ks], bKh + off);
                ldsm4(bl4[ks], bKl + off);
            }
            #pragma unroll
            for (int half=0; half<2; half++){
                #pragma unroll
                for (int mt=0;mt<2;mt++){
                    float Dr[4] = {0.f,0.f,0.f,0.f};
                    #pragma unroll
                    for (int ks=0;ks<4;ks++){
                        const unsigned* bhf = &bh4[ks][half*2];
                        const unsigned* blf = &bl4[ks][half*2];
                        mma16816(Dr, qh_f[mt][ks], bhf);
                        mma16816(Dr, qh_f[mt][ks], blf);
                        mma16816(Dr, ql_f[mt][ks], bhf);
                    }
                    rmax[mt][0] = fmaxf(rmax[mt][0], fmaxf(Dr[0], Dr[1]));
                    rmax[mt][1] = fmaxf(rmax[mt][1], fmaxf(Dr[2], Dr[3]));
                }
            }
        }
        __syncthreads();
    }
    #pragma unroll
    for (int off=1; off<4; off<<=1){
        #pragma unroll
        for (int mt=0;mt<2;mt++){
            rmax[mt][0] = fmaxf(rmax[mt][0], __shfl_xor_sync(0xffffffffu, rmax[mt][0], off));
            rmax[mt][1] = fmaxf(rmax[mt][1], __shfl_xor_sync(0xffffffffu, rmax[mt][1], off));
        }
    }
    if ((lid&3)==0){
        #pragma unroll
        for (int mt=0;mt<2;mt++){
            int ql = wm*32 + mt*16 + (lid>>2);
            qmw[wn][ql]   = rmax[mt][0];
            qmw[wn][ql+8] = rmax[mt][1];
        }
    }
    __syncthreads();
    if (tid < 128){
        float mx = fmaxf(qmw[0][tid], qmw[1][tid]);
        const float* qrow = g_Q + ((size_t)bh*Ss + q0 + tid)*64;
        float dot = 0.f;
        #pragma unroll
        for (int c=0;c<16;c++){
            float4 qv = *(const float4*)(qrow + c*4);
            dot += qv.x*Km[c*4] + qv.y*Km[c*4+1] + qv.z*Km[c*4+2] + qv.w*Km[c*4+3];
        }
        g_imp[(size_t)bh*Ss + q0 + tid] = (mx - dot)*SCALE;
    }
}

// ---------------- top-U per (b,h): shfl-based iterative argmax, tie -> lower index ----------------
__global__ void topk_kernel(){
    int bh = blockIdx.x;
    int tid = threadIdx.x, lid = tid&31, wid = tid>>5;
    __shared__ float vals[Ss];
    __shared__ float wv[8];
    __shared__ int   wi[8];
    for (int s=tid;s<Ss;s+=256){ vals[s]=g_imp[(size_t)bh*Ss+s]; g_selu[(size_t)bh*Ss+s]=-1; }
    __syncthreads();
    for (int it=0; it<Uu; it++){
        float bv=-INFINITY; int bi=Ss;
        #pragma unroll
        for (int j=0;j<8;j++){
            int s = tid + j*256;
            float v = vals[s];
            if (v>bv){ bv=v; bi=s; }
        }
        #pragma unroll
        for (int off=16; off>0; off>>=1){
            float v2 = __shfl_down_sync(0xffffffffu, bv, off);
            int   i2 = __shfl_down_sync(0xffffffffu, bi, off);
            if (v2>bv || (v2==bv && i2<bi)){ bv=v2; bi=i2; }
        }
        if (lid==0){ wv[wid]=bv; wi[wid]=bi; }
        __syncthreads();
        if (wid==0){
            float v = (lid<8) ? wv[lid] : -INFINITY;
            int   i = (lid<8) ? wi[lid] : Ss;
            #pragma unroll
            for (int off=4; off>0; off>>=1){
                float v2 = __shfl_down_sync(0xffffffffu, v, off);
                int   i2 = __shfl_down_sync(0xffffffffu, i, off);
                if (v2>v || (v2==v && i2<i)){ v=v2; i=i2; }
            }
            if (lid==0){
                g_selidx[bh*Uu+it]=i;
                g_selu[(size_t)bh*Ss+i]=it;
                vals[i]=-INFINITY;
            }
        }
        __syncthreads();
    }
}

// ---------------- attention partials: grid (bh, ugroup, ksplit) ----------------
__global__ __launch_bounds__(256) void attn_part(){
    extern __shared__ float dsm[];
    float* sc   = dsm;                    // [19][1024]
    float* Qs   = dsm + UG*1024;          // [19][64]
    float* accg = Qs  + UG*64;            // [4][19][64]
    float* ml   = accg + 4*UG*64;         // [19][2]
    int bh = blockIdx.x, ug = blockIdx.y, ks = blockIdx.z;
    int tid = threadIdx.x, lid = tid&31, wid = tid>>5;
    const float* K = g_K + ((size_t)bh*Ss + ks*1024)*64;
    const float* V = g_V + ((size_t)bh*Ss + ks*1024)*64;

    for (int e=tid; e<UG*64; e+=256){
        int u = e>>6, d = e&63;
        int sq = g_selidx[bh*Uu + ug*UG + u];
        Qs[e] = g_Q[((size_t)bh*Ss + sq)*64 + d];
    }
    __syncthreads();

    for (int e=tid; e<UG*1024; e+=256){
        int q = e>>10, k = e&1023;
        const float4* kr = (const float4*)(K + (size_t)k*64);
        const float4* qr = (const float4*)(Qs + q*64);
        float d_ = 0.f;
        #pragma unroll
        for (int c=0;c<16;c++){
            float4 kv = kr[c], qv = qr[c];
            d_ += kv.x*qv.x + kv.y*qv.y + kv.z*qv.z + kv.w*qv.w;
        }
        sc[e] = d_*SCALE;
    }
    __syncthreads();

    for (int r=0;r<3;r++){
        int q = r*8 + wid;
        if (q < UG){
            float* row = sc + q*1024;
            float m = -INFINITY;
            #pragma unroll
            for (int j=0;j<32;j++) m = fmaxf(m, row[lid + 32*j]);
            #pragma unroll
            for (int off=16; off>0; off>>=1) m = fmaxf(m, __shfl_xor_sync(0xffffffffu, m, off));
            float l = 0.f;
            #pragma unroll
            for (int j=0;j<32;j++){
                float e_ = expf(row[lid + 32*j] - m);
                row[lid + 32*j] = e_;
                l += e_;
            }
            #pragma unroll
            for (int off=16; off>0; off>>=1) l += __shfl_xor_sync(0xffffffffu, l, off);
            if (lid==0){ ml[q*2]=m; ml[q*2+1]=l; }
        }
    }
    __syncthreads();

    {
        int d = tid & 63, g = tid >> 6;
        float acc[UG];
        #pragma unroll
        for (int u=0;u<UG;u++) acc[u]=0.f;
        for (int k=g*256; k<g*256+256; k++){
            float vv = V[(size_t)k*64 + d];
            #pragma unroll
            for (int u=0;u<UG;u++) acc[u] += sc[u*1024 + k]*vv;
        }
        #pragma unroll
        for (int u=0;u<UG;u++) accg[(g*UG+u)*64 + d] = acc[u];
    }
    __syncthreads();

    for (int e=tid; e<UG*64; e+=256){
        int u = e>>6, d = e&63;
        float a = accg[(0*UG+u)*64+d] + accg[(1*UG+u)*64+d]
                + accg[(2*UG+u)*64+d] + accg[(3*UG+u)*64+d];
        g_part[bh][ug*UG+u][ks][2+d] = a;
    }
    if (tid < UG){
        g_part[bh][ug*UG+tid][ks][0] = ml[tid*2];
        g_part[bh][ug*UG+tid][ks][1] = ml[tid*2+1];
    }
}

// ---------------- merge the 2 key-split partials ----------------
__global__ void attn_merge(){
    int idx = blockIdx.x;
    int d = threadIdx.x;
    int bh = idx/Uu, u = idx%Uu;
    float m1 = g_part[bh][u][0][0], l1 = g_part[bh][u][0][1];
    float m2 = g_part[bh][u][1][0], l2 = g_part[bh][u][1][1];
    float m = fmaxf(m1,m2);
    float w1 = expf(m1-m), w2 = expf(m2-m);
    float l = l1*w1 + l2*w2 + 1e-8f;
    float a = g_part[bh][u][0][2+d]*w1 + g_part[bh][u][1][2+d]*w2;
    g_outsel[(size_t)idx*64 + d] = a/l;
}

// ---------------- base[b][:] = meanVcat[b] @ Wo^T + bo ----------------
__global__ void base_kernel(const float* __restrict__ Wo, const float* __restrict__ bo){
    int b = blockIdx.y;
    int j = blockIdx.x*256 + threadIdx.x;
    __shared__ float mv[Dd];
    for (int d=threadIdx.x; d<Dd; d+=256) mv[d] = g_Vmean[b*Dd + d];
    __syncthreads();
    float acc = bo[j];
    const float* wr = Wo + (size_t)j*Dd;
    for (int d=0; d<Dd; d+=4){
        float4 w = *(const float4*)(wr+d);
        acc += w.x*mv[d] + w.y*mv[d+1] + w.z*mv[d+2] + w.w*mv[d+3];
    }
    g_base[b*Dd + j] = acc;
}

// ---------------- output assembly: base + sparse rank-64 corrections ----------------
__global__ __launch_bounds__(256) void out_kernel(const float* __restrict__ Wo, float* __restrict__ out){
    int row = blockIdx.x;
    int b = row >> 11, s = row & 2047;
    int tid = threadIdx.x;
    float acc[4];
    #pragma unroll
    for (int r=0;r<4;r++) acc[r] = g_base[b*Dd + tid + r*256];
    __shared__ float delta[64];
    for (int h=0;h<Hh;h++){
        int u = g_selu[((size_t)(b*Hh+h))*Ss + s];
        if (u>=0){
            if (tid<64) delta[tid] = g_outsel[((b*Hh+h)*Uu+u)*64 + tid] - g_Vmean[(b*Hh+h)*64 + tid];
            __syncthreads();
            #pragma unroll
            for (int r=0;r<4;r++){
                int j = tid + r*256;
                const float* wr = Wo + (size_t)j*Dd + h*64;
                float a=0.f;
                #pragma unroll
                for (int k=0;k<64;k+=4){
                    float4 w=*(const float4*)(wr+k);
                    a += w.x*delta[k]+w.y*delta[k+1]+w.z*delta[k+2]+w.w*delta[k+3];
                }
                acc[r]+=a;
            }
            __syncthreads();
        }
    }
    #pragma unroll
    for (int r=0;r<4;r++) out[(size_t)row*Dd + tid + r*256] = acc[r];
}

// ---------------- launch ----------------
extern "C" void kernel_launch(void* const* d_in, const int* in_sizes, int n_in,
                              void* d_out, int out_size){
    const float* q  = (const float*)d_in[0];
    const float* k  = (const float*)d_in[1];
    const float* v  = (const float*)d_in[2];
    const float* Wq = (const float*)d_in[3];
    const float* bq = (const float*)d_in[4];
    const float* Wk = (const float*)d_in[5];
    const float* bk = (const float*)d_in[6];
    const float* Wv = (const float*)d_in[7];
    const float* bv = (const float*)d_in[8];
    const float* Wo = (const float*)d_in[9];
    const float* bo = (const float*)d_in[10];
    float* out = (float*)d_out;

    cudaFuncSetAttribute(scan_mma, cudaFuncAttributeMaxDynamicSharedMemorySize, 4*128*72*2);
    int attn_smem = (UG*1024 + UG*64 + 4*UG*64 + UG*2)*4;
    cudaFuncSetAttribute(attn_part, cudaFuncAttributeMaxDynamicSharedMemorySize, attn_smem);

    split_in3<<<dim3(NIN/4/256, 3),256>>>(q, k, v);
    split_w3 <<<dim3(NW/4/256, 3),256>>>(Wq, Wk, Wv);

    dim3 pg(NR/128, Dd/128);
    proj_mma<<<pg,256>>>(bq, 0);
    proj_mma<<<pg,256>>>(bk, 1);
    proj_mma<<<pg,256>>>(bv, 2);
    mean_part<<<dim3(64,8),256>>>();
    mean_final<<<64,64>>>();
    scan_mma<<<dim3(Ss/128, Bb*Hh),256, 4*128*72*2>>>();
    topk_kernel<<<Bb*Hh,256>>>();
    attn_part<<<dim3(64,2,2),256, attn_smem>>>();
    attn_merge<<<Bb*Hh*Uu,64>>>();
    base_kernel<<<dim3(Dd/256, Bb),256>>>(Wo, bo);
    out_kernel<<<NR,256>>>(Wo, out);
}